// round 5
// baseline (speedup 1.0000x reference)
#include <cuda_runtime.h>
#include <cuda_bf16.h>
#include <cstdint>

// ---------------------------------------------------------------------------
// Problem constants
// ---------------------------------------------------------------------------
#define CCN   256
#define STD   12
#define FS    64
#define HALF  32
#define NIMG  (CCN*STD)          // 3072
#define DIM   2048               // FS*HALF
#define IMGE  (FS*FS)            // 4096

static const size_t T_FULL  = (size_t)NIMG * IMGE;
static const size_t T_SLICE = (size_t)CCN * 11 * IMGE;

// Output section offsets (floats)
static const size_t S0 = 0;                    // x
static const size_t S1 = S0 + T_FULL;          // phiX
static const size_t S2 = S1 + T_FULL;          // dephiPhiX
static const size_t S3 = S2 + T_FULL;          // kPhix
static const size_t S4 = S3 + T_FULL;          // dePhiKPhiX
static const size_t S5 = S4 + T_FULL;          // x[:,1:]
static const size_t S6 = S5 + T_SLICE;         // phiX[:,1:]

// ---------------------------------------------------------------------------
// Scratch (device globals — no runtime allocation allowed)
// ---------------------------------------------------------------------------
__device__ float  g_A [(size_t)NIMG * DIM];    // fp32 activations (also wtrans scratch)
__device__ float  g_B [(size_t)NIMG * DIM];
__device__ int8_t g_qA1[(size_t)NIMG * DIM];   // activation int8 plane 1
__device__ int8_t g_qA2[(size_t)NIMG * DIM];   // activation int8 plane 2
__device__ float  g_sA [NIMG];                 // activation row scales
__device__ int8_t g_qW1a[(size_t)DIM * DIM];   // W1^T int8 planes [N,K]
__device__ int8_t g_qW1b[(size_t)DIM * DIM];
__device__ float  g_sW1 [DIM];
__device__ int8_t g_qW3a[(size_t)DIM * DIM];
__device__ int8_t g_qW3b[(size_t)DIM * DIM];
__device__ float  g_sW3 [DIM];
__device__ float  g_aF[DIM], g_cF[DIM], g_aG[DIM], g_cG[DIM];

// ---------------------------------------------------------------------------
// Helpers (base sm_103 target — no arch-'a' features)
// ---------------------------------------------------------------------------
__device__ __forceinline__ uint32_t smem_u32(const void* p) {
    uint32_t a;
    asm("{ .reg .u64 t; cvta.to.shared.u64 t, %1; cvt.u32.u64 %0, t; }" : "=r"(a) : "l"(p));
    return a;
}

__device__ __forceinline__ void cp16(uint32_t saddr, const void* gptr) {
    asm volatile("cp.async.cg.shared.global [%0], [%1], 16;" :: "r"(saddr), "l"(gptr));
}
#define CP_COMMIT() asm volatile("cp.async.commit_group;" ::: "memory")
#define CP_WAIT(n)  asm volatile("cp.async.wait_group %0;" :: "n"(n) : "memory")

__device__ __forceinline__ void ldsm4(uint32_t* r, uint32_t addr) {
    asm volatile("ldmatrix.sync.aligned.m8n8.x4.shared.b16 {%0,%1,%2,%3}, [%4];"
                 : "=r"(r[0]), "=r"(r[1]), "=r"(r[2]), "=r"(r[3]) : "r"(addr));
}

__device__ __forceinline__ void mma_s8(int* d, const uint32_t* a, const uint32_t* b) {
    asm volatile(
        "mma.sync.aligned.m16n8k32.row.col.s32.s8.s8.s32 "
        "{%0,%1,%2,%3}, {%4,%5,%6,%7}, {%8,%9}, {%0,%1,%2,%3};"
        : "+r"(d[0]), "+r"(d[1]), "+r"(d[2]), "+r"(d[3])
        : "r"(a[0]), "r"(a[1]), "r"(a[2]), "r"(a[3]), "r"(b[0]), "r"(b[1]));
}

// quantize v into (q1, q2): v ~= s*(q1 + q2/128)
__device__ __forceinline__ void quant2(float v, float s, float inv_s,
                                       int8_t& q1, int8_t& q2) {
    int a = __float2int_rn(v * inv_s);
    a = max(-127, min(127, a));
    float r = v - (float)a * s;
    int b = __float2int_rn(r * inv_s * 128.0f);
    b = max(-127, min(127, b));
    q1 = (int8_t)a;
    q2 = (int8_t)b;
}

// block-wide max over 256 threads (each contributes one value)
__device__ __forceinline__ float blockmax256(float v, float* red) {
    #pragma unroll
    for (int o = 16; o > 0; o >>= 1)
        v = fmaxf(v, __shfl_xor_sync(0xFFFFFFFFu, v, o));
    int wid = threadIdx.x >> 5, lane = threadIdx.x & 31;
    if (lane == 0) red[wid] = v;
    __syncthreads();
    if (wid == 0) {
        float m = (lane < 8) ? red[lane] : 0.0f;
        #pragma unroll
        for (int o = 4; o > 0; o >>= 1)
            m = fmaxf(m, __shfl_xor_sync(0xFFFFFFFFu, m, o));
        if (lane == 0) red[0] = m;
    }
    __syncthreads();
    return red[0];
}

// ---------------------------------------------------------------------------
// BN coefficient precompute
// ---------------------------------------------------------------------------
__global__ void bncoef_kernel(const float* __restrict__ g1, const float* __restrict__ be1,
                              const float* __restrict__ m1, const float* __restrict__ v1,
                              const float* __restrict__ g3, const float* __restrict__ be3,
                              const float* __restrict__ m3, const float* __restrict__ v3)
{
    int k = blockIdx.x * blockDim.x + threadIdx.x;
    if (k < DIM) {
        float aF = g1[k] * rsqrtf(v1[k] + 1e-3f);
        g_aF[k] = aF;  g_cF[k] = be1[k] - aF * m1[k];
        float aG = g3[k] * rsqrtf(v3[k] + 1e-3f);
        g_aG[k] = aG;  g_cG[k] = be3[k] - aG * m3[k];
    }
}

// ---------------------------------------------------------------------------
// Weight transpose: W [K,N] -> WT fp32 [N,K] (into scratch)
// ---------------------------------------------------------------------------
__global__ void wtrans_kernel(const float* __restrict__ W, float* __restrict__ WT)
{
    __shared__ float t[32][33];
    int bn = blockIdx.x * 32;
    int bk = blockIdx.y * 32;
    int tx = threadIdx.x, ty = threadIdx.y;   // 32 x 8
    #pragma unroll
    for (int i = 0; i < 32; i += 8)
        t[ty + i][tx] = W[(size_t)(bk + ty + i) * DIM + bn + tx];
    __syncthreads();
    #pragma unroll
    for (int i = 0; i < 32; i += 8)
        WT[(size_t)(bn + ty + i) * DIM + bk + tx] = t[tx][ty + i];
}

// ---------------------------------------------------------------------------
// Weight row quantization: WT [N,K] -> int8 planes + per-row scale
// one block per row n
// ---------------------------------------------------------------------------
__global__ void wq_kernel(const float* __restrict__ WT, int8_t* __restrict__ Q1,
                          int8_t* __restrict__ Q2, float* __restrict__ sW)
{
    __shared__ float red[32];
    int n = blockIdx.x;
    const float* row = WT + (size_t)n * DIM;
    float v[8];
    float mx = 0.0f;
    #pragma unroll
    for (int j = 0; j < 8; j++) {
        v[j] = row[threadIdx.x + j * 256];
        mx = fmaxf(mx, fabsf(v[j]));
    }
    mx = blockmax256(mx, red);
    float s = fmaxf(mx, 1e-30f) / 127.0f;
    float inv_s = 127.0f / fmaxf(mx, 1e-30f);
    if (threadIdx.x == 0) sW[n] = s;
    #pragma unroll
    for (int j = 0; j < 8; j++) {
        int e = threadIdx.x + j * 256;
        int8_t q1, q2;
        quant2(v[j], s, inv_s, q1, q2);
        Q1[(size_t)n * DIM + e] = q1;
        Q2[(size_t)n * DIM + e] = q2;
    }
}

// ---------------------------------------------------------------------------
// Checkerboard split + BN + int8 quant of one half. One block per image n.
// ---------------------------------------------------------------------------
__global__ void qsplit_kernel(const float* __restrict__ x, float* __restrict__ u1,
                              float* __restrict__ u2,
                              const float* __restrict__ aC, const float* __restrict__ cC,
                              int8_t* __restrict__ Q1, int8_t* __restrict__ Q2,
                              float* __restrict__ sA, int prep_first)
{
    __shared__ float red[32];
    int n = blockIdx.x;
    const float* img = x + ((size_t)n << 12);
    float sv[8];
    float mx = 0.0f;
    #pragma unroll
    for (int j = 0; j < 8; j++) {
        int e = threadIdx.x + j * 256;
        int i = e >> 5, jj = e & 31, p = i & 1;
        const float* row = img + (i << 6) + (jj << 1);
        float v1 = row[p];
        float v2 = row[1 - p];
        u1[(size_t)n * DIM + e] = v1;
        u2[(size_t)n * DIM + e] = v2;
        float s = aC[e] * (prep_first ? v1 : v2) + cC[e];
        sv[j] = s;
        mx = fmaxf(mx, fabsf(s));
    }
    mx = blockmax256(mx, red);
    float s = fmaxf(mx, 1e-30f) / 127.0f;
    float inv_s = 127.0f / fmaxf(mx, 1e-30f);
    if (threadIdx.x == 0) sA[n] = s;
    #pragma unroll
    for (int j = 0; j < 8; j++) {
        int e = threadIdx.x + j * 256;
        int8_t q1, q2;
        quant2(sv[j], s, inv_s, q1, q2);
        Q1[(size_t)n * DIM + e] = q1;
        Q2[(size_t)n * DIM + e] = q2;
    }
}

// ---------------------------------------------------------------------------
// Flat row BN + int8 quant (for second GEMM of each pair). Block per row.
// ---------------------------------------------------------------------------
__global__ void qflat_kernel(const float* __restrict__ X,
                             const float* __restrict__ aC, const float* __restrict__ cC,
                             int8_t* __restrict__ Q1, int8_t* __restrict__ Q2,
                             float* __restrict__ sA)
{
    __shared__ float red[32];
    int n = blockIdx.x;
    const float* row = X + (size_t)n * DIM;
    float sv[8];
    float mx = 0.0f;
    #pragma unroll
    for (int j = 0; j < 8; j++) {
        int e = threadIdx.x + j * 256;
        float s = aC[e] * row[e] + cC[e];
        sv[j] = s;
        mx = fmaxf(mx, fabsf(s));
    }
    mx = blockmax256(mx, red);
    float s = fmaxf(mx, 1e-30f) / 127.0f;
    float inv_s = 127.0f / fmaxf(mx, 1e-30f);
    if (threadIdx.x == 0) sA[n] = s;
    #pragma unroll
    for (int j = 0; j < 8; j++) {
        int e = threadIdx.x + j * 256;
        int8_t q1, q2;
        quant2(sv[j], s, inv_s, q1, q2);
        Q1[(size_t)n * DIM + e] = q1;
        Q2[(size_t)n * DIM + e] = q2;
    }
}

// ---------------------------------------------------------------------------
// Mix (+ optional fused [:,1:] slice)
// ---------------------------------------------------------------------------
__global__ void mix_kernel(const float* __restrict__ v1b, const float* __restrict__ w2b,
                           float* __restrict__ y, float* __restrict__ ysl)
{
    size_t idx = (size_t)blockIdx.x * blockDim.x + threadIdx.x;
    if (idx >= (size_t)NIMG * IMGE) return;
    int n = (int)(idx >> 12);
    int r = (int)((idx >> 6) & 63);
    int c = (int)(idx & 63);
    const float* v1 = v1b + ((size_t)n << 11) + ((size_t)r << 5);
    const float* w2 = w2b + ((size_t)n << 11) + ((size_t)r << 5);
    float val;
    if ((r & 1) == 0) {
        val = (c & 1) ? w2[(c - 1) >> 1] : v1[c >> 1];
    } else {
        val = (c & 1) ? v1[((c + 1) >> 1) & 31] : w2[((c >> 1) + 31) & 31];
    }
    y[idx] = val;
    if (ysl) {
        int s = n % STD;
        if (s >= 1) {
            int cc = n / STD;
            size_t e = idx & 4095;
            ysl[((size_t)(cc * 11 + s - 1) << 12) + e] = val;
        }
    }
}

// ---------------------------------------------------------------------------
// Copy x + fused x[:,1:] slice
// ---------------------------------------------------------------------------
__global__ void copyslice_kernel(const float* __restrict__ x, float* __restrict__ dst,
                                 float* __restrict__ dsl)
{
    size_t idx = (size_t)blockIdx.x * blockDim.x + threadIdx.x;
    if (idx >= T_FULL) return;
    float v = x[idx];
    dst[idx] = v;
    int n = (int)(idx >> 12);
    int s = n % STD;
    if (s >= 1) {
        int cc = n / STD;
        size_t e = idx & 4095;
        dsl[((size_t)(cc * 11 + s - 1) << 12) + e] = v;
    }
}

// ---------------------------------------------------------------------------
// Koopman step
// ---------------------------------------------------------------------------
__global__ void koop_kernel(const float* __restrict__ phi, const float* __restrict__ kop,
                            float* __restrict__ outk)
{
    __shared__ float sk[64][64];
    __shared__ float si[64][64];
    int m = blockIdx.x;
    int nprime = m / STD, s = m % STD;
    int q = nprime >> 2, b = nprime & 3;
    int nin = b * 64 + q;
    const float* src = phi + (size_t)(nin * STD + s) * IMGE;
    float* dst = outk + (size_t)m * IMGE;
    int t = threadIdx.x;
    for (int e = t; e < IMGE; e += 256) {
        sk[e >> 6][e & 63] = kop[e];
        si[e >> 6][e & 63] = src[e];
    }
    __syncthreads();
    for (int e = t; e < IMGE; e += 256) {
        int i = e >> 6, c = e & 63;
        float acc = 0.f;
        #pragma unroll
        for (int j = 0; j < 64; j++) acc += si[i][j] * sk[j][c];
        dst[e] = acc;
    }
}

// ---------------------------------------------------------------------------
// INT8 two-plane GEMM (m16n8k32.s8 + ldmatrix).
//   out[m,n] = base[m,n] + sign*( sa[m]*sw[n]*(acc1 + acc2/128) + bias[n] )
// A planes [M,K] int8 q1/q2 with row scale sa; W planes [N,K] q1/q2, col scale sw.
// CTA tile 128x128, BK=64 int8, 8 warps (2x4), warp tile 64x32, 3-stage cp.async.
// SMEM rows: 64B data + 16B pad (pitch 80B) -> conflict-free ldmatrix.
// ---------------------------------------------------------------------------
#define GM 128
#define GN 128
#define BKI 64                     // int8 elements per k-tile
#define NT_K (DIM / BKI)           // 32
#define PITCHB 80
#define PLANE_B (128 * PITCHB)     // 10240
#define STAGE_B (4 * PLANE_B)      // 40960
#define STAGES 3
#define SM_TOTAL (STAGES * STAGE_B)

__global__ void __launch_bounds__(256, 1)
gemm_i8_kernel(const int8_t* __restrict__ Aq1, const int8_t* __restrict__ Aq2,
               const float* __restrict__ sA,
               const int8_t* __restrict__ Wq1, const int8_t* __restrict__ Wq2,
               const float* __restrict__ sW,
               const float* __restrict__ bias, const float* base, float* outp, float sign)
{
    extern __shared__ char smem[];
    uint32_t sb = smem_u32(smem);
    const int tid  = threadIdx.x;
    const int wid  = tid >> 5;
    const int lane = tid & 31;
    const int gid  = lane >> 2;      // 0..7
    const int tig  = lane & 3;       // 0..3
    const int warpM = wid >> 2;      // 0..1
    const int warpN = wid & 3;       // 0..3
    const int m0 = blockIdx.y * GM;
    const int n0 = blockIdx.x * GN;

    int acc1[4][4][4], acc2[4][4][4];
    #pragma unroll
    for (int i = 0; i < 4; i++)
        #pragma unroll
        for (int j = 0; j < 4; j++)
            #pragma unroll
            for (int c = 0; c < 4; c++) { acc1[i][j][c] = 0; acc2[i][j][c] = 0; }

    const int t8 = lane >> 3;
    const int r8 = lane & 7;
    const uint32_t aoff = (uint32_t)((warpM * 64 + (t8 & 1) * 8 + r8) * PITCHB + (t8 >> 1) * 16);
    const uint32_t boff = (uint32_t)(2 * PLANE_B +
                          (warpN * 32 + (t8 >> 1) * 8 + r8) * PITCHB + (t8 & 1) * 16);

    // loader: 2048 x 16B chunks per k-tile (4 planes x 128 rows x 64B)
    auto load_tile = [&](int s, int t) {
        const int k0 = t * BKI;
        uint32_t stage = sb + (uint32_t)(s * STAGE_B);
        #pragma unroll
        for (int j = 0; j < 8; j++) {
            int c = tid + j * 256;
            int pl = c >> 9;
            int cc = c & 511;
            int row = cc >> 2;
            int c4  = cc & 3;
            const int8_t* g;
            if (pl == 0)      g = Aq1 + (size_t)(m0 + row) * DIM + k0 + c4 * 16;
            else if (pl == 1) g = Aq2 + (size_t)(m0 + row) * DIM + k0 + c4 * 16;
            else if (pl == 2) g = Wq1 + (size_t)(n0 + row) * DIM + k0 + c4 * 16;
            else              g = Wq2 + (size_t)(n0 + row) * DIM + k0 + c4 * 16;
            cp16(stage + (uint32_t)(pl * PLANE_B + row * PITCHB + c4 * 16), g);
        }
    };

    #pragma unroll
    for (int s = 0; s < STAGES; s++) {
        load_tile(s, s);
        CP_COMMIT();
    }

    for (int t = 0; t < NT_K; t++) {
        CP_WAIT(2);
        __syncthreads();
        uint32_t stg = sb + (uint32_t)((t % STAGES) * STAGE_B);
        uint32_t aB = stg + aoff;
        uint32_t bB = stg + boff;

        #pragma unroll
        for (int kk = 0; kk < BKI; kk += 32) {
            uint32_t A1[4][4], A2[4][4], B1[4][2], B2[4][2];
            #pragma unroll
            for (int mi = 0; mi < 4; mi++) {
                uint32_t a = aB + (uint32_t)(mi * 16 * PITCHB + kk);
                ldsm4(A1[mi], a);
                ldsm4(A2[mi], a + PLANE_B);
            }
            #pragma unroll
            for (int nip = 0; nip < 2; nip++) {
                uint32_t b = bB + (uint32_t)(nip * 16 * PITCHB + kk);
                uint32_t t1[4], t2[4];
                ldsm4(t1, b);
                ldsm4(t2, b + PLANE_B);
                B1[nip * 2][0] = t1[0]; B1[nip * 2][1] = t1[1];
                B1[nip * 2 + 1][0] = t1[2]; B1[nip * 2 + 1][1] = t1[3];
                B2[nip * 2][0] = t2[0]; B2[nip * 2][1] = t2[1];
                B2[nip * 2 + 1][0] = t2[2]; B2[nip * 2 + 1][1] = t2[3];
            }
            #pragma unroll
            for (int mi = 0; mi < 4; mi++)
                #pragma unroll
                for (int ni = 0; ni < 4; ni++) {
                    mma_s8(acc1[mi][ni], A1[mi], B1[ni]);
                    mma_s8(acc2[mi][ni], A1[mi], B2[ni]);
                    mma_s8(acc2[mi][ni], A2[mi], B1[ni]);
                }
        }
        __syncthreads();
        if (t + STAGES < NT_K) load_tile(t % STAGES, t + STAGES);
        CP_COMMIT();
    }

    // ---- epilogue ----
    #pragma unroll
    for (int mi = 0; mi < 4; mi++) {
        #pragma unroll
        for (int half = 0; half < 2; half++) {
            size_t m = (size_t)(m0 + warpM * 64 + mi * 16 + gid + half * 8);
            float sa = sA[m];
            #pragma unroll
            for (int ni = 0; ni < 4; ni++) {
                int n = n0 + warpN * 32 + ni * 8 + 2 * tig;
                float2 sw = *(const float2*)(sW + n);
                float v0 = sa * sw.x * ((float)acc1[mi][ni][half * 2 + 0] +
                                        (float)acc2[mi][ni][half * 2 + 0] * 0.0078125f);
                float v1 = sa * sw.y * ((float)acc1[mi][ni][half * 2 + 1] +
                                        (float)acc2[mi][ni][half * 2 + 1] * 0.0078125f);
                float2 bs = *(const float2*)(bias + n);
                float2 bb = *(const float2*)(base + m * DIM + n);
                float2 o;
                o.x = bb.x + sign * (v0 + bs.x);
                o.y = bb.y + sign * (v1 + bs.y);
                *(float2*)(outp + m * DIM + n) = o;
            }
        }
    }
}

// ---------------------------------------------------------------------------
extern "C" void kernel_launch(void* const* d_in, const int* in_sizes, int n_in,
                              void* d_out, int out_size)
{
    const float* x   = (const float*)d_in[0];
    const float* W1  = (const float*)d_in[2];
    const float* b1  = (const float*)d_in[3];
    const float* g1  = (const float*)d_in[4];
    const float* be1 = (const float*)d_in[5];
    const float* m1  = (const float*)d_in[6];
    const float* v1  = (const float*)d_in[7];
    const float* W3  = (const float*)d_in[8];
    const float* b3  = (const float*)d_in[9];
    const float* g3  = (const float*)d_in[10];
    const float* be3 = (const float*)d_in[11];
    const float* m3  = (const float*)d_in[12];
    const float* v3  = (const float*)d_in[13];
    const float* kop = (const float*)d_in[14];
    float* out = (float*)d_out;

    float *A, *B, *sA, *sW1, *sW3, *aF, *cF, *aG, *cG;
    int8_t *qA1, *qA2, *qW1a, *qW1b, *qW3a, *qW3b;
    cudaGetSymbolAddress((void**)&A,    g_A);
    cudaGetSymbolAddress((void**)&B,    g_B);
    cudaGetSymbolAddress((void**)&qA1,  g_qA1);
    cudaGetSymbolAddress((void**)&qA2,  g_qA2);
    cudaGetSymbolAddress((void**)&sA,   g_sA);
    cudaGetSymbolAddress((void**)&qW1a, g_qW1a);
    cudaGetSymbolAddress((void**)&qW1b, g_qW1b);
    cudaGetSymbolAddress((void**)&sW1,  g_sW1);
    cudaGetSymbolAddress((void**)&qW3a, g_qW3a);
    cudaGetSymbolAddress((void**)&qW3b, g_qW3b);
    cudaGetSymbolAddress((void**)&sW3,  g_sW3);
    cudaGetSymbolAddress((void**)&aF, g_aF);
    cudaGetSymbolAddress((void**)&cF, g_cF);
    cudaGetSymbolAddress((void**)&aG, g_aG);
    cudaGetSymbolAddress((void**)&cG, g_cG);

    static int smem_set = 0;
    if (!smem_set) {
        cudaFuncSetAttribute(gemm_i8_kernel, cudaFuncAttributeMaxDynamicSharedMemorySize,
                             SM_TOTAL);
        smem_set = 1;
    }

    dim3 ggrid(DIM / GN, NIMG / GM);           // (16, 24)
    const int MIX_BLKS  = (int)(((size_t)NIMG * IMGE + 255) / 256);
    const int FULL_BLKS = (int)((T_FULL + 255) / 256);
    dim3 wgrid(DIM / 32, DIM / 32), wblk(32, 8);

    bncoef_kernel<<<8, 256>>>(g1, be1, m1, v1, g3, be3, m3, v3);

    // Weight prep: transpose into fp32 scratch (g_A, free at this point), then quantize.
    wtrans_kernel<<<wgrid, wblk>>>(W1, A);
    wq_kernel<<<DIM, 256>>>(A, qW1a, qW1b, sW1);
    wtrans_kernel<<<wgrid, wblk>>>(W3, A);
    wq_kernel<<<DIM, 256>>>(A, qW3a, qW3b, sW3);

    copyslice_kernel<<<FULL_BLKS, 256>>>(x, out + S0, out + S5);

    // ---- Encoder ----
    qsplit_kernel<<<NIMG, 256>>>(x, A, B, aF, cF, qA1, qA2, sA, 0);   // A=u1, B=u2, q=BN_F(u2)
    gemm_i8_kernel<<<ggrid, 256, SM_TOTAL>>>(qA1, qA2, sA, qW1a, qW1b, sW1,
                                             b1, A, A, +1.0f);        // A = v1
    qflat_kernel<<<NIMG, 256>>>(A, aG, cG, qA1, qA2, sA);             // q = BN_G(v1)
    gemm_i8_kernel<<<ggrid, 256, SM_TOTAL>>>(qA1, qA2, sA, qW3a, qW3b, sW3,
                                             b3, B, B, +1.0f);        // B = w2
    mix_kernel<<<MIX_BLKS, 256>>>(A, B, out + S1, out + S6);          // phiX, phiX[:,1:]

    // ---- Decoder(phiX) ----
    qsplit_kernel<<<NIMG, 256>>>(out + S1, A, B, aG, cG, qA1, qA2, sA, 1); // A=w1,B=w2,q=BN_G(w1)
    gemm_i8_kernel<<<ggrid, 256, SM_TOTAL>>>(qA1, qA2, sA, qW3a, qW3b, sW3,
                                             b3, B, B, -1.0f);        // B = v2
    qflat_kernel<<<NIMG, 256>>>(B, aF, cF, qA1, qA2, sA);             // q = BN_F(v2)
    gemm_i8_kernel<<<ggrid, 256, SM_TOTAL>>>(qA1, qA2, sA, qW1a, qW1b, sW1,
                                             b1, A, A, -1.0f);        // A = u1
    mix_kernel<<<MIX_BLKS, 256>>>(A, B, out + S2, nullptr);           // dephiPhiX

    // ---- Koopman ----
    koop_kernel<<<NIMG, 256>>>(out + S1, kop, out + S3);              // kPhix

    // ---- Decoder(kPhix) ----
    qsplit_kernel<<<NIMG, 256>>>(out + S3, A, B, aG, cG, qA1, qA2, sA, 1);
    gemm_i8_kernel<<<ggrid, 256, SM_TOTAL>>>(qA1, qA2, sA, qW3a, qW3b, sW3,
                                             b3, B, B, -1.0f);
    qflat_kernel<<<NIMG, 256>>>(B, aF, cF, qA1, qA2, sA);
    gemm_i8_kernel<<<ggrid, 256, SM_TOTAL>>>(qA1, qA2, sA, qW1a, qW1b, sW1,
                                             b1, A, A, -1.0f);
    mix_kernel<<<MIX_BLKS, 256>>>(A, B, out + S4, nullptr);           // dePhiKPhiX
}

// round 6
// speedup vs baseline: 2.3529x; 2.3529x over previous
#include <cuda_runtime.h>
#include <cuda_bf16.h>
#include <cstdint>

// ---------------------------------------------------------------------------
// Problem constants
// ---------------------------------------------------------------------------
#define CCN   256
#define STD   12
#define FS    64
#define HALF  32
#define NIMG  (CCN*STD)          // 3072
#define DIM   2048               // FS*HALF
#define IMGE  (FS*FS)            // 4096

static const size_t T_FULL  = (size_t)NIMG * IMGE;
static const size_t T_SLICE = (size_t)CCN * 11 * IMGE;

// Output section offsets (floats)
static const size_t S0 = 0;                    // x
static const size_t S1 = S0 + T_FULL;          // phiX
static const size_t S2 = S1 + T_FULL;          // dephiPhiX
static const size_t S3 = S2 + T_FULL;          // kPhix
static const size_t S4 = S3 + T_FULL;          // dePhiKPhiX
static const size_t S5 = S4 + T_FULL;          // x[:,1:]
static const size_t S6 = S5 + T_SLICE;         // phiX[:,1:]

// ---------------------------------------------------------------------------
// Scratch (device globals — no runtime allocation allowed)
// ---------------------------------------------------------------------------
__device__ float         g_A [(size_t)NIMG * DIM];
__device__ float         g_B [(size_t)NIMG * DIM];
__device__ __nv_bfloat16 g_H0[(size_t)NIMG * DIM];
__device__ __nv_bfloat16 g_L0[(size_t)NIMG * DIM];
__device__ __nv_bfloat16 g_H1[(size_t)NIMG * DIM];
__device__ __nv_bfloat16 g_L1[(size_t)NIMG * DIM];
__device__ __nv_bfloat16 g_W1Thi[(size_t)DIM * DIM];   // W1^T hi  [N,K]
__device__ __nv_bfloat16 g_W1Tlo[(size_t)DIM * DIM];
__device__ __nv_bfloat16 g_W3Thi[(size_t)DIM * DIM];
__device__ __nv_bfloat16 g_W3Tlo[(size_t)DIM * DIM];
__device__ float g_aF[DIM], g_cF[DIM], g_aG[DIM], g_cG[DIM];

// ---------------------------------------------------------------------------
// Helpers (base sm_103 target only — NO tcgen05 / arch-'a' features)
// ---------------------------------------------------------------------------
__device__ __forceinline__ uint32_t smem_u32(const void* p) {
    uint32_t a;
    asm("{ .reg .u64 t; cvta.to.shared.u64 t, %1; cvt.u32.u64 %0, t; }" : "=r"(a) : "l"(p));
    return a;
}

__device__ __forceinline__ void cp16(uint32_t saddr, const void* gptr) {
    asm volatile("cp.async.cg.shared.global [%0], [%1], 16;" :: "r"(saddr), "l"(gptr));
}
#define CP_COMMIT() asm volatile("cp.async.commit_group;" ::: "memory")
#define CP_WAIT(n)  asm volatile("cp.async.wait_group %0;" :: "n"(n) : "memory")

__device__ __forceinline__ void ldsm4(uint32_t* r, uint32_t addr) {
    asm volatile("ldmatrix.sync.aligned.m8n8.x4.shared.b16 {%0,%1,%2,%3}, [%4];"
                 : "=r"(r[0]), "=r"(r[1]), "=r"(r[2]), "=r"(r[3]) : "r"(addr));
}

__device__ __forceinline__ void mma_bf16(float* d, const uint32_t* a, const uint32_t* b) {
    asm volatile(
        "mma.sync.aligned.m16n8k16.row.col.f32.bf16.bf16.f32 "
        "{%0,%1,%2,%3}, {%4,%5,%6,%7}, {%8,%9}, {%0,%1,%2,%3};"
        : "+f"(d[0]), "+f"(d[1]), "+f"(d[2]), "+f"(d[3])
        : "r"(a[0]), "r"(a[1]), "r"(a[2]), "r"(a[3]), "r"(b[0]), "r"(b[1]));
}

__device__ __forceinline__ void bf16split(float s, __nv_bfloat16& h, __nv_bfloat16& l) {
    h = __float2bfloat16(s);
    l = __float2bfloat16(s - __bfloat162float(h));
}

// ---------------------------------------------------------------------------
// BN coefficient precompute
// ---------------------------------------------------------------------------
__global__ void bncoef_kernel(const float* __restrict__ g1, const float* __restrict__ be1,
                              const float* __restrict__ m1, const float* __restrict__ v1,
                              const float* __restrict__ g3, const float* __restrict__ be3,
                              const float* __restrict__ m3, const float* __restrict__ v3)
{
    int k = blockIdx.x * blockDim.x + threadIdx.x;
    if (k < DIM) {
        float aF = g1[k] * rsqrtf(v1[k] + 1e-3f);
        g_aF[k] = aF;  g_cF[k] = be1[k] - aF * m1[k];
        float aG = g3[k] * rsqrtf(v3[k] + 1e-3f);
        g_aG[k] = aG;  g_cG[k] = be3[k] - aG * m3[k];
    }
}

// ---------------------------------------------------------------------------
// Weight prep: W [K,N] -> W^T [N,K] split into bf16 hi/lo planes
// ---------------------------------------------------------------------------
__global__ void wprep_kernel(const float* __restrict__ W, __nv_bfloat16* __restrict__ Thi,
                             __nv_bfloat16* __restrict__ Tlo)
{
    __shared__ float t[32][33];
    int bn = blockIdx.x * 32;
    int bk = blockIdx.y * 32;
    int tx = threadIdx.x, ty = threadIdx.y;   // 32 x 8
    #pragma unroll
    for (int i = 0; i < 32; i += 8)
        t[ty + i][tx] = W[(size_t)(bk + ty + i) * DIM + bn + tx];
    __syncthreads();
    #pragma unroll
    for (int i = 0; i < 32; i += 8) {
        float v = t[tx][ty + i];
        size_t o = (size_t)(bn + ty + i) * DIM + bk + tx;
        __nv_bfloat16 h, l;
        bf16split(v, h, l);
        Thi[o] = h;
        Tlo[o] = l;
    }
}

// ---------------------------------------------------------------------------
// Checkerboard split + BN + bf16 hi/lo prep of one half
// ---------------------------------------------------------------------------
__global__ void split_prep_kernel(const float* __restrict__ x, float* __restrict__ u1,
                                  float* __restrict__ u2,
                                  const float* __restrict__ aC, const float* __restrict__ cC,
                                  __nv_bfloat16* __restrict__ hi,
                                  __nv_bfloat16* __restrict__ lo,
                                  int prep_first)
{
    size_t idx = (size_t)blockIdx.x * blockDim.x + threadIdx.x;
    if (idx >= (size_t)NIMG * DIM) return;
    int n = (int)(idx >> 11);
    int i = (int)((idx >> 5) & 63);
    int j = (int)(idx & 31);
    int p = i & 1;
    const float* row = x + ((size_t)n << 12) + ((size_t)i << 6) + ((size_t)j << 1);
    float v1 = row[p];
    float v2 = row[1 - p];
    u1[idx] = v1;
    u2[idx] = v2;
    int k = (int)(idx & 2047);
    float s = aC[k] * (prep_first ? v1 : v2) + cC[k];
    __nv_bfloat16 h, l;
    bf16split(s, h, l);
    hi[idx] = h;
    lo[idx] = l;
}

// ---------------------------------------------------------------------------
// Mix (+ optional fused [:,1:] slice of the mixed tensor)
// ---------------------------------------------------------------------------
__global__ void mix_kernel(const float* __restrict__ v1b, const float* __restrict__ w2b,
                           float* __restrict__ y, float* __restrict__ ysl)
{
    size_t idx = (size_t)blockIdx.x * blockDim.x + threadIdx.x;
    if (idx >= (size_t)NIMG * IMGE) return;
    int n = (int)(idx >> 12);
    int r = (int)((idx >> 6) & 63);
    int c = (int)(idx & 63);
    const float* v1 = v1b + ((size_t)n << 11) + ((size_t)r << 5);
    const float* w2 = w2b + ((size_t)n << 11) + ((size_t)r << 5);
    float val;
    if ((r & 1) == 0) {
        val = (c & 1) ? w2[(c - 1) >> 1] : v1[c >> 1];
    } else {
        val = (c & 1) ? v1[((c + 1) >> 1) & 31] : w2[((c >> 1) + 31) & 31];
    }
    y[idx] = val;
    if (ysl) {
        int s = n % STD;
        if (s >= 1) {
            int cc = n / STD;
            size_t e = idx & 4095;
            ysl[((size_t)(cc * 11 + s - 1) << 12) + e] = val;
        }
    }
}

// ---------------------------------------------------------------------------
// Copy x to out section 0 and write x[:,1:] slice in the same pass
// ---------------------------------------------------------------------------
__global__ void copyslice_kernel(const float* __restrict__ x, float* __restrict__ dst,
                                 float* __restrict__ dsl)
{
    size_t idx = (size_t)blockIdx.x * blockDim.x + threadIdx.x;
    if (idx >= T_FULL) return;
    float v = x[idx];
    dst[idx] = v;
    int n = (int)(idx >> 12);
    int s = n % STD;
    if (s >= 1) {
        int cc = n / STD;
        size_t e = idx & 4095;
        dsl[((size_t)(cc * 11 + s - 1) << 12) + e] = v;
    }
}

// ---------------------------------------------------------------------------
// Koopman step — register-tiled 64x64 @ 64x64 per block.
// Image tile stored TRANSPOSED (pitch 68) so fragment loads are float4 +
// broadcast; kop row-major. 16x16 threads, 4x4 outputs each. FFMA-bound.
// ---------------------------------------------------------------------------
__global__ void __launch_bounds__(256)
koop_kernel(const float* __restrict__ phi, const float* __restrict__ kop,
            float* __restrict__ outk)
{
    __shared__ float sk[64 * 64];     // [j][c]
    __shared__ float si[64 * 68];     // transposed [j][i], pitch 68
    int m = blockIdx.x;
    int nprime = m / STD, s = m % STD;
    int q = nprime >> 2, b = nprime & 3;
    int nin = b * 64 + q;
    const float* src = phi + (size_t)(nin * STD + s) * IMGE;
    float* dst = outk + (size_t)m * IMGE;
    int t = threadIdx.x;

    #pragma unroll
    for (int e = t * 4; e < IMGE; e += 1024)
        *(float4*)(sk + e) = *(const float4*)(kop + e);
    #pragma unroll
    for (int e = t; e < IMGE; e += 256) {
        int i = e >> 6, j = e & 63;
        si[j * 68 + i] = src[e];
    }
    __syncthreads();

    int tr = t >> 4, tc = t & 15;
    float acc[4][4];
    #pragma unroll
    for (int a = 0; a < 4; a++)
        #pragma unroll
        for (int bb = 0; bb < 4; bb++) acc[a][bb] = 0.f;

    const float* siP = si + tr * 4;
    const float* skP = sk + tc * 4;
    #pragma unroll 4
    for (int j = 0; j < 64; j++) {
        float4 av = *(const float4*)(siP + j * 68);   // rows tr*4..+3, col j
        float4 bv = *(const float4*)(skP + j * 64);   // row j, cols tc*4..+3
        acc[0][0] += av.x * bv.x; acc[0][1] += av.x * bv.y;
        acc[0][2] += av.x * bv.z; acc[0][3] += av.x * bv.w;
        acc[1][0] += av.y * bv.x; acc[1][1] += av.y * bv.y;
        acc[1][2] += av.y * bv.z; acc[1][3] += av.y * bv.w;
        acc[2][0] += av.z * bv.x; acc[2][1] += av.z * bv.y;
        acc[2][2] += av.z * bv.z; acc[2][3] += av.z * bv.w;
        acc[3][0] += av.w * bv.x; acc[3][1] += av.w * bv.y;
        acc[3][2] += av.w * bv.z; acc[3][3] += av.w * bv.w;
    }
    #pragma unroll
    for (int dr = 0; dr < 4; dr++) {
        float4 o = make_float4(acc[dr][0], acc[dr][1], acc[dr][2], acc[dr][3]);
        *(float4*)(dst + (tr * 4 + dr) * 64 + tc * 4) = o;
    }
}

// ---------------------------------------------------------------------------
// BF16x3 mma.sync GEMM (m16n8k16 + ldmatrix).
//   out[m,n] = base[m,n] + sign*( sum_k A[m,k]*WT[n,k] + bias[n] )
// CTA tile 128x128, BK=32, 8 warps (2x4), warp tile 64x32.
// 2-stage cp.async pipeline, 80KB smem -> 2 CTAs per SM.
// SMEM rows pitch 80B (64B data + 16B pad) -> conflict-free ldmatrix.
// ---------------------------------------------------------------------------
#define GM 128
#define GN 128
#define BK 32
#define NT_K (DIM / BK)            // 64
#define PITCHB 80                  // bytes per smem row
#define PLANE_B (128 * PITCHB)     // 10240
#define STAGE_B (4 * PLANE_B)      // 40960
#define STAGES 2
#define SM_TOTAL (STAGES * STAGE_B)   // 81920

__global__ void __launch_bounds__(256, 2)
gemm_tc_kernel(const __nv_bfloat16* __restrict__ Ahi, const __nv_bfloat16* __restrict__ Alo,
               const __nv_bfloat16* __restrict__ Whi, const __nv_bfloat16* __restrict__ Wlo,
               const float* __restrict__ bias, const float* base, float* outp, float sign,
               const float* __restrict__ aN, const float* __restrict__ cN,
               __nv_bfloat16* eHi, __nv_bfloat16* eLo, int emit)
{
    extern __shared__ char smem[];
    uint32_t sb = smem_u32(smem);
    const int tid  = threadIdx.x;
    const int wid  = tid >> 5;
    const int lane = tid & 31;
    const int gid  = lane >> 2;      // 0..7
    const int tig  = lane & 3;       // 0..3
    const int warpM = wid >> 2;      // 0..1
    const int warpN = wid & 3;       // 0..3
    const int m0 = blockIdx.y * GM;
    const int n0 = blockIdx.x * GN;

    float acc[4][4][4];
    #pragma unroll
    for (int i = 0; i < 4; i++)
        #pragma unroll
        for (int j = 0; j < 4; j++)
            #pragma unroll
            for (int c = 0; c < 4; c++) acc[i][j][c] = 0.f;

    const int t8 = lane >> 3;
    const int r8 = lane & 7;
    const uint32_t aoff = (uint32_t)((warpM * 64 + (t8 & 1) * 8 + r8) * PITCHB + (t8 >> 1) * 16);
    const uint32_t boff = (uint32_t)(2 * PLANE_B +
                          (warpN * 32 + (t8 >> 1) * 8 + r8) * PITCHB + (t8 & 1) * 16);

    auto load_tile = [&](int s, int t) {
        const int k0 = t * BK;
        uint32_t stage = sb + (uint32_t)(s * STAGE_B);
        #pragma unroll
        for (int j = 0; j < 8; j++) {
            int c = tid + j * 256;
            int pl = c >> 9;
            int cc = c & 511;
            int row = cc >> 2;
            int c4  = cc & 3;
            const __nv_bfloat16* g;
            if (pl == 0)      g = Ahi + (size_t)(m0 + row) * DIM + k0 + c4 * 8;
            else if (pl == 1) g = Alo + (size_t)(m0 + row) * DIM + k0 + c4 * 8;
            else if (pl == 2) g = Whi + (size_t)(n0 + row) * DIM + k0 + c4 * 8;
            else              g = Wlo + (size_t)(n0 + row) * DIM + k0 + c4 * 8;
            cp16(stage + (uint32_t)(pl * PLANE_B + row * PITCHB + c4 * 16), g);
        }
    };

    #pragma unroll
    for (int s = 0; s < STAGES; s++) {
        load_tile(s, s);
        CP_COMMIT();
    }

    for (int t = 0; t < NT_K; t++) {
        CP_WAIT(1);
        __syncthreads();
        uint32_t stg = sb + (uint32_t)((t % STAGES) * STAGE_B);
        uint32_t aB = stg + aoff;
        uint32_t bB = stg + boff;

        #pragma unroll
        for (int kk = 0; kk < BK; kk += 16) {
            uint32_t Ah[4][4], Al[4][4], Bh[4][2], Bl[4][2];
            #pragma unroll
            for (int mi = 0; mi < 4; mi++) {
                uint32_t a = aB + (uint32_t)(mi * 16 * PITCHB + kk * 2);
                ldsm4(Ah[mi], a);
                ldsm4(Al[mi], a + PLANE_B);
            }
            #pragma unroll
            for (int nip = 0; nip < 2; nip++) {
                uint32_t b = bB + (uint32_t)(nip * 16 * PITCHB + kk * 2);
                uint32_t th[4], tl[4];
                ldsm4(th, b);
                ldsm4(tl, b + PLANE_B);
                Bh[nip * 2][0] = th[0]; Bh[nip * 2][1] = th[1];
                Bh[nip * 2 + 1][0] = th[2]; Bh[nip * 2 + 1][1] = th[3];
                Bl[nip * 2][0] = tl[0]; Bl[nip * 2][1] = tl[1];
                Bl[nip * 2 + 1][0] = tl[2]; Bl[nip * 2 + 1][1] = tl[3];
            }
            #pragma unroll
            for (int mi = 0; mi < 4; mi++)
                #pragma unroll
                for (int ni = 0; ni < 4; ni++) {
                    mma_bf16(acc[mi][ni], Ah[mi], Bh[ni]);
                    mma_bf16(acc[mi][ni], Ah[mi], Bl[ni]);
                    mma_bf16(acc[mi][ni], Al[mi], Bh[ni]);
                }
        }
        __syncthreads();
        if (t + STAGES < NT_K) load_tile(t % STAGES, t + STAGES);
        CP_COMMIT();
    }

    // ---- epilogue ----
    #pragma unroll
    for (int mi = 0; mi < 4; mi++) {
        #pragma unroll
        for (int half = 0; half < 2; half++) {
            size_t m = (size_t)(m0 + warpM * 64 + mi * 16 + gid + half * 8);
            #pragma unroll
            for (int ni = 0; ni < 4; ni++) {
                int n = n0 + warpN * 32 + ni * 8 + 2 * tig;
                float r0 = acc[mi][ni][half * 2 + 0];
                float r1 = acc[mi][ni][half * 2 + 1];
                float2 bs = *(const float2*)(bias + n);
                float2 bb = *(const float2*)(base + m * DIM + n);
                float2 o;
                o.x = bb.x + sign * (r0 + bs.x);
                o.y = bb.y + sign * (r1 + bs.y);
                *(float2*)(outp + m * DIM + n) = o;
                if (emit) {
                    float2 a2 = *(const float2*)(aN + n);
                    float2 c2 = *(const float2*)(cN + n);
                    float s0 = a2.x * o.x + c2.x;
                    float s1 = a2.y * o.y + c2.y;
                    __nv_bfloat162 h2, l2;
                    bf16split(s0, h2.x, l2.x);
                    bf16split(s1, h2.y, l2.y);
                    *(__nv_bfloat162*)(eHi + m * DIM + n) = h2;
                    *(__nv_bfloat162*)(eLo + m * DIM + n) = l2;
                }
            }
        }
    }
}

// ---------------------------------------------------------------------------
extern "C" void kernel_launch(void* const* d_in, const int* in_sizes, int n_in,
                              void* d_out, int out_size)
{
    const float* x   = (const float*)d_in[0];
    const float* W1  = (const float*)d_in[2];
    const float* b1  = (const float*)d_in[3];
    const float* g1  = (const float*)d_in[4];
    const float* be1 = (const float*)d_in[5];
    const float* m1  = (const float*)d_in[6];
    const float* v1  = (const float*)d_in[7];
    const float* W3  = (const float*)d_in[8];
    const float* b3  = (const float*)d_in[9];
    const float* g3  = (const float*)d_in[10];
    const float* be3 = (const float*)d_in[11];
    const float* m3  = (const float*)d_in[12];
    const float* v3  = (const float*)d_in[13];
    const float* kop = (const float*)d_in[14];
    float* out = (float*)d_out;

    float *A, *B, *aF, *cF, *aG, *cG;
    __nv_bfloat16 *H0, *L0, *H1, *L1, *W1h, *W1l, *W3h, *W3l;
    cudaGetSymbolAddress((void**)&A,  g_A);
    cudaGetSymbolAddress((void**)&B,  g_B);
    cudaGetSymbolAddress((void**)&H0, g_H0);
    cudaGetSymbolAddress((void**)&L0, g_L0);
    cudaGetSymbolAddress((void**)&H1, g_H1);
    cudaGetSymbolAddress((void**)&L1, g_L1);
    cudaGetSymbolAddress((void**)&W1h, g_W1Thi);
    cudaGetSymbolAddress((void**)&W1l, g_W1Tlo);
    cudaGetSymbolAddress((void**)&W3h, g_W3Thi);
    cudaGetSymbolAddress((void**)&W3l, g_W3Tlo);
    cudaGetSymbolAddress((void**)&aF, g_aF);
    cudaGetSymbolAddress((void**)&cF, g_cF);
    cudaGetSymbolAddress((void**)&aG, g_aG);
    cudaGetSymbolAddress((void**)&cG, g_cG);

    static int smem_set = 0;
    if (!smem_set) {
        cudaFuncSetAttribute(gemm_tc_kernel, cudaFuncAttributeMaxDynamicSharedMemorySize,
                             SM_TOTAL);
        smem_set = 1;
    }

    dim3 ggrid(DIM / GN, NIMG / GM);           // (16, 24)
    const int SPLIT_BLKS = (int)(((size_t)NIMG * DIM + 255) / 256);
    const int MIX_BLKS   = (int)(((size_t)NIMG * IMGE + 255) / 256);
    const int FULL_BLKS  = (int)((T_FULL + 255) / 256);
    dim3 wgrid(DIM / 32, DIM / 32), wblk(32, 8);

    bncoef_kernel<<<8, 256>>>(g1, be1, m1, v1, g3, be3, m3, v3);
    wprep_kernel<<<wgrid, wblk>>>(W1, W1h, W1l);
    wprep_kernel<<<wgrid, wblk>>>(W3, W3h, W3l);

    copyslice_kernel<<<FULL_BLKS, 256>>>(x, out + S0, out + S5);

    // ---- Encoder ----
    split_prep_kernel<<<SPLIT_BLKS, 256>>>(x, A, B, aF, cF, H0, L0, 0);
    gemm_tc_kernel<<<ggrid, 256, SM_TOTAL>>>(H0, L0, W1h, W1l, b1, A, A, +1.0f,
                                             aG, cG, H1, L1, 1);
    gemm_tc_kernel<<<ggrid, 256, SM_TOTAL>>>(H1, L1, W3h, W3l, b3, B, B, +1.0f,
                                             aF, cF, H0, L0, 0);
    mix_kernel<<<MIX_BLKS, 256>>>(A, B, out + S1, out + S6);   // phiX + phiX[:,1:]

    // ---- Decoder(phiX) ----
    split_prep_kernel<<<SPLIT_BLKS, 256>>>(out + S1, A, B, aG, cG, H0, L0, 1);
    gemm_tc_kernel<<<ggrid, 256, SM_TOTAL>>>(H0, L0, W3h, W3l, b3, B, B, -1.0f,
                                             aF, cF, H1, L1, 1);
    gemm_tc_kernel<<<ggrid, 256, SM_TOTAL>>>(H1, L1, W1h, W1l, b1, A, A, -1.0f,
                                             aF, cF, H0, L0, 0);
    mix_kernel<<<MIX_BLKS, 256>>>(A, B, out + S2, nullptr);    // dephiPhiX

    // ---- Koopman ----
    koop_kernel<<<NIMG, 256>>>(out + S1, kop, out + S3);       // kPhix

    // ---- Decoder(kPhix) ----
    split_prep_kernel<<<SPLIT_BLKS, 256>>>(out + S3, A, B, aG, cG, H0, L0, 1);
    gemm_tc_kernel<<<ggrid, 256, SM_TOTAL>>>(H0, L0, W3h, W3l, b3, B, B, -1.0f,
                                             aF, cF, H1, L1, 1);
    gemm_tc_kernel<<<ggrid, 256, SM_TOTAL>>>(H1, L1, W1h, W1l, b1, A, A, -1.0f,
                                             aF, cF, H0, L0, 0);
    mix_kernel<<<MIX_BLKS, 256>>>(A, B, out + S4, nullptr);    // dePhiKPhiX
}

// round 7
// speedup vs baseline: 2.4621x; 1.0464x over previous
#include <cuda_runtime.h>
#include <cuda_bf16.h>
#include <cstdint>

// ---------------------------------------------------------------------------
// Problem constants
// ---------------------------------------------------------------------------
#define CCN   256
#define STD   12
#define FS    64
#define HALF  32
#define NIMG  (CCN*STD)          // 3072
#define DIM   2048               // FS*HALF
#define IMGE  (FS*FS)            // 4096

static const size_t T_FULL  = (size_t)NIMG * IMGE;
static const size_t T_SLICE = (size_t)CCN * 11 * IMGE;

// Output section offsets (floats)
static const size_t S0 = 0;                    // x
static const size_t S1 = S0 + T_FULL;          // phiX
static const size_t S2 = S1 + T_FULL;          // dephiPhiX
static const size_t S3 = S2 + T_FULL;          // kPhix
static const size_t S4 = S3 + T_FULL;          // dePhiKPhiX
static const size_t S5 = S4 + T_FULL;          // x[:,1:]
static const size_t S6 = S5 + T_SLICE;         // phiX[:,1:]

// ---------------------------------------------------------------------------
// Scratch (device globals — no runtime allocation allowed)
// ---------------------------------------------------------------------------
__device__ float         g_A [(size_t)NIMG * DIM];
__device__ float         g_B [(size_t)NIMG * DIM];
__device__ __nv_bfloat16 g_H0[(size_t)NIMG * DIM];
__device__ __nv_bfloat16 g_L0[(size_t)NIMG * DIM];
__device__ __nv_bfloat16 g_H1[(size_t)NIMG * DIM];
__device__ __nv_bfloat16 g_L1[(size_t)NIMG * DIM];
__device__ __nv_bfloat16 g_W1Thi[(size_t)DIM * DIM];   // W1^T hi  [N,K]
__device__ __nv_bfloat16 g_W1Tlo[(size_t)DIM * DIM];
__device__ __nv_bfloat16 g_W3Thi[(size_t)DIM * DIM];
__device__ __nv_bfloat16 g_W3Tlo[(size_t)DIM * DIM];
__device__ float g_aF[DIM], g_cF[DIM], g_aG[DIM], g_cG[DIM];

// ---------------------------------------------------------------------------
// Helpers (base sm_103 target only — NO tcgen05 / arch-'a' features)
// ---------------------------------------------------------------------------
__device__ __forceinline__ uint32_t smem_u32(const void* p) {
    uint32_t a;
    asm("{ .reg .u64 t; cvta.to.shared.u64 t, %1; cvt.u32.u64 %0, t; }" : "=r"(a) : "l"(p));
    return a;
}

__device__ __forceinline__ void cp16(uint32_t saddr, const void* gptr) {
    asm volatile("cp.async.cg.shared.global [%0], [%1], 16;" :: "r"(saddr), "l"(gptr));
}
#define CP_COMMIT() asm volatile("cp.async.commit_group;" ::: "memory")
#define CP_WAIT(n)  asm volatile("cp.async.wait_group %0;" :: "n"(n) : "memory")

__device__ __forceinline__ void ldsm4(uint32_t* r, uint32_t addr) {
    asm volatile("ldmatrix.sync.aligned.m8n8.x4.shared.b16 {%0,%1,%2,%3}, [%4];"
                 : "=r"(r[0]), "=r"(r[1]), "=r"(r[2]), "=r"(r[3]) : "r"(addr));
}

__device__ __forceinline__ void mma_bf16(float* d, const uint32_t* a, const uint32_t* b) {
    asm volatile(
        "mma.sync.aligned.m16n8k16.row.col.f32.bf16.bf16.f32 "
        "{%0,%1,%2,%3}, {%4,%5,%6,%7}, {%8,%9}, {%0,%1,%2,%3};"
        : "+f"(d[0]), "+f"(d[1]), "+f"(d[2]), "+f"(d[3])
        : "r"(a[0]), "r"(a[1]), "r"(a[2]), "r"(a[3]), "r"(b[0]), "r"(b[1]));
}

__device__ __forceinline__ void bf16split(float s, __nv_bfloat16& h, __nv_bfloat16& l) {
    h = __float2bfloat16(s);
    l = __float2bfloat16(s - __bfloat162float(h));
}

// ---------------------------------------------------------------------------
// BN coefficient precompute
// ---------------------------------------------------------------------------
__global__ void bncoef_kernel(const float* __restrict__ g1, const float* __restrict__ be1,
                              const float* __restrict__ m1, const float* __restrict__ v1,
                              const float* __restrict__ g3, const float* __restrict__ be3,
                              const float* __restrict__ m3, const float* __restrict__ v3)
{
    int k = blockIdx.x * blockDim.x + threadIdx.x;
    if (k < DIM) {
        float aF = g1[k] * rsqrtf(v1[k] + 1e-3f);
        g_aF[k] = aF;  g_cF[k] = be1[k] - aF * m1[k];
        float aG = g3[k] * rsqrtf(v3[k] + 1e-3f);
        g_aG[k] = aG;  g_cG[k] = be3[k] - aG * m3[k];
    }
}

// ---------------------------------------------------------------------------
// Weight prep: W [K,N] -> W^T [N,K] split into bf16 hi/lo planes
// ---------------------------------------------------------------------------
__global__ void wprep_kernel(const float* __restrict__ W, __nv_bfloat16* __restrict__ Thi,
                             __nv_bfloat16* __restrict__ Tlo)
{
    __shared__ float t[32][33];
    int bn = blockIdx.x * 32;
    int bk = blockIdx.y * 32;
    int tx = threadIdx.x, ty = threadIdx.y;   // 32 x 8
    #pragma unroll
    for (int i = 0; i < 32; i += 8)
        t[ty + i][tx] = W[(size_t)(bk + ty + i) * DIM + bn + tx];
    __syncthreads();
    #pragma unroll
    for (int i = 0; i < 32; i += 8) {
        float v = t[tx][ty + i];
        size_t o = (size_t)(bn + ty + i) * DIM + bk + tx;
        __nv_bfloat16 h, l;
        bf16split(v, h, l);
        Thi[o] = h;
        Tlo[o] = l;
    }
}

// ---------------------------------------------------------------------------
// Checkerboard split + BN + bf16 hi/lo prep of one half (float4 vectorized)
// One thread handles 4 consecutive j positions.
// ---------------------------------------------------------------------------
__global__ void split_prep_kernel(const float* __restrict__ x, float* __restrict__ u1,
                                  float* __restrict__ u2,
                                  const float* __restrict__ aC, const float* __restrict__ cC,
                                  __nv_bfloat16* __restrict__ hi,
                                  __nv_bfloat16* __restrict__ lo,
                                  int prep_first)
{
    size_t q = (size_t)blockIdx.x * blockDim.x + threadIdx.x;   // quad index
    if (q >= (size_t)NIMG * DIM / 4) return;
    size_t idx = q * 4;
    int n = (int)(idx >> 11);
    int i = (int)((idx >> 5) & 63);
    int j0 = (int)(idx & 31);                 // multiple of 4
    int p = i & 1;
    const float* row = x + ((size_t)n << 12) + ((size_t)i << 6) + (j0 << 1);
    float4 a = *(const float4*)(row);         // x cols 2j0 .. 2j0+3
    float4 b = *(const float4*)(row + 4);     // x cols 2j0+4 .. 2j0+7
    float4 f1, f2;
    if (p == 0) { f1 = make_float4(a.x, a.z, b.x, b.z); f2 = make_float4(a.y, a.w, b.y, b.w); }
    else        { f1 = make_float4(a.y, a.w, b.y, b.w); f2 = make_float4(a.x, a.z, b.x, b.z); }
    *(float4*)(u1 + idx) = f1;
    *(float4*)(u2 + idx) = f2;
    int k = (int)(idx & 2047);
    float4 av = *(const float4*)(aC + k);
    float4 cv = *(const float4*)(cC + k);
    float4 src = prep_first ? f1 : f2;
    float s0 = av.x * src.x + cv.x;
    float s1 = av.y * src.y + cv.y;
    float s2 = av.z * src.z + cv.z;
    float s3 = av.w * src.w + cv.w;
    __nv_bfloat162 h01, l01, h23, l23;
    bf16split(s0, h01.x, l01.x); bf16split(s1, h01.y, l01.y);
    bf16split(s2, h23.x, l23.x); bf16split(s3, h23.y, l23.y);
    uint2 hv, lv;
    hv.x = *(uint32_t*)&h01; hv.y = *(uint32_t*)&h23;
    lv.x = *(uint32_t*)&l01; lv.y = *(uint32_t*)&l23;
    *(uint2*)(hi + idx) = hv;
    *(uint2*)(lo + idx) = lv;
}

// ---------------------------------------------------------------------------
// Mix (+ optional fused [:,1:] slice) — float4 stores
// ---------------------------------------------------------------------------
__global__ void mix_kernel(const float* __restrict__ v1b, const float* __restrict__ w2b,
                           float* __restrict__ y, float* __restrict__ ysl)
{
    size_t q = (size_t)blockIdx.x * blockDim.x + threadIdx.x;
    if (q >= (size_t)NIMG * IMGE / 4) return;
    size_t idx = q * 4;
    int n = (int)(idx >> 12);
    int r = (int)((idx >> 6) & 63);
    int c0 = (int)(idx & 63);                 // multiple of 4
    int h = c0 >> 1;                          // even
    const float* v1 = v1b + ((size_t)n << 11) + ((size_t)r << 5);
    const float* w2 = w2b + ((size_t)n << 11) + ((size_t)r << 5);
    float4 o;
    if ((r & 1) == 0) {
        float2 vv = *(const float2*)(v1 + h);
        float2 ww = *(const float2*)(w2 + h);
        o = make_float4(vv.x, ww.x, vv.y, ww.y);
    } else {
        o.x = w2[(h + 31) & 31];
        o.y = v1[(h + 1) & 31];
        o.z = w2[h];
        o.w = v1[(h + 2) & 31];
    }
    *(float4*)(y + idx) = o;
    if (ysl) {
        int s = n % STD;
        if (s >= 1) {
            int cc = n / STD;
            size_t e = idx & 4095;
            *(float4*)(ysl + ((size_t)(cc * 11 + s - 1) << 12) + e) = o;
        }
    }
}

// ---------------------------------------------------------------------------
// Copy x + fused x[:,1:] slice — float4
// ---------------------------------------------------------------------------
__global__ void copyslice_kernel(const float* __restrict__ x, float* __restrict__ dst,
                                 float* __restrict__ dsl)
{
    size_t q = (size_t)blockIdx.x * blockDim.x + threadIdx.x;
    if (q >= T_FULL / 4) return;
    size_t idx = q * 4;
    float4 v = *(const float4*)(x + idx);
    *(float4*)(dst + idx) = v;
    int n = (int)(idx >> 12);
    int s = n % STD;
    if (s >= 1) {
        int cc = n / STD;
        size_t e = idx & 4095;
        *(float4*)(dsl + ((size_t)(cc * 11 + s - 1) << 12) + e) = v;
    }
}

// ---------------------------------------------------------------------------
// Koopman step — register-tiled 64x64 @ 64x64 per block (verified R6)
// ---------------------------------------------------------------------------
__global__ void __launch_bounds__(256)
koop_kernel(const float* __restrict__ phi, const float* __restrict__ kop,
            float* __restrict__ outk)
{
    __shared__ float sk[64 * 64];
    __shared__ float si[64 * 68];
    int m = blockIdx.x;
    int nprime = m / STD, s = m % STD;
    int q = nprime >> 2, b = nprime & 3;
    int nin = b * 64 + q;
    const float* src = phi + (size_t)(nin * STD + s) * IMGE;
    float* dst = outk + (size_t)m * IMGE;
    int t = threadIdx.x;

    #pragma unroll
    for (int e = t * 4; e < IMGE; e += 1024)
        *(float4*)(sk + e) = *(const float4*)(kop + e);
    #pragma unroll
    for (int e = t; e < IMGE; e += 256) {
        int i = e >> 6, j = e & 63;
        si[j * 68 + i] = src[e];
    }
    __syncthreads();

    int tr = t >> 4, tc = t & 15;
    float acc[4][4];
    #pragma unroll
    for (int a = 0; a < 4; a++)
        #pragma unroll
        for (int bb = 0; bb < 4; bb++) acc[a][bb] = 0.f;

    const float* siP = si + tr * 4;
    const float* skP = sk + tc * 4;
    #pragma unroll 4
    for (int j = 0; j < 64; j++) {
        float4 av = *(const float4*)(siP + j * 68);
        float4 bv = *(const float4*)(skP + j * 64);
        acc[0][0] += av.x * bv.x; acc[0][1] += av.x * bv.y;
        acc[0][2] += av.x * bv.z; acc[0][3] += av.x * bv.w;
        acc[1][0] += av.y * bv.x; acc[1][1] += av.y * bv.y;
        acc[1][2] += av.y * bv.z; acc[1][3] += av.y * bv.w;
        acc[2][0] += av.z * bv.x; acc[2][1] += av.z * bv.y;
        acc[2][2] += av.z * bv.z; acc[2][3] += av.z * bv.w;
        acc[3][0] += av.w * bv.x; acc[3][1] += av.w * bv.y;
        acc[3][2] += av.w * bv.z; acc[3][3] += av.w * bv.w;
    }
    #pragma unroll
    for (int dr = 0; dr < 4; dr++) {
        float4 o = make_float4(acc[dr][0], acc[dr][1], acc[dr][2], acc[dr][3]);
        *(float4*)(dst + (tr * 4 + dr) * 64 + tc * 4) = o;
    }
}

// ---------------------------------------------------------------------------
// BF16x3 mma.sync GEMM (m16n8k16 + ldmatrix).
// CTA tile 96x128 (512 tiles -> two FULL waves at 2 CTAs/SM), BK=32,
// 8 warps (2x4), warp tile 48x32, 2-stage cp.async, 70KB smem.
// ---------------------------------------------------------------------------
#define GM 96
#define GN 128
#define BK 32
#define NT_K (DIM / BK)              // 64
#define PITCHB 80                    // bytes per smem row
#define APLANE_B (96 * PITCHB)       // 7680
#define BPLANE_B (128 * PITCHB)      // 10240
#define STAGE_B (2*APLANE_B + 2*BPLANE_B)   // 35840
#define STAGES 2
#define SM_TOTAL (STAGES * STAGE_B)  // 71680
#define NCHUNK (2*96*4 + 2*128*4)    // 1792 16B chunks per stage

__global__ void __launch_bounds__(256, 2)
gemm_tc_kernel(const __nv_bfloat16* __restrict__ Ahi, const __nv_bfloat16* __restrict__ Alo,
               const __nv_bfloat16* __restrict__ Whi, const __nv_bfloat16* __restrict__ Wlo,
               const float* __restrict__ bias, const float* base, float* outp, float sign,
               const float* __restrict__ aN, const float* __restrict__ cN,
               __nv_bfloat16* eHi, __nv_bfloat16* eLo, int emit)
{
    extern __shared__ char smem[];
    uint32_t sb = smem_u32(smem);
    const int tid  = threadIdx.x;
    const int wid  = tid >> 5;
    const int lane = tid & 31;
    const int gid  = lane >> 2;
    const int tig  = lane & 3;
    const int warpM = wid >> 2;      // 0..1 (48 rows each)
    const int warpN = wid & 3;       // 0..3 (32 cols each)
    const int m0 = blockIdx.y * GM;
    const int n0 = blockIdx.x * GN;

    float acc[3][4][4];
    #pragma unroll
    for (int i = 0; i < 3; i++)
        #pragma unroll
        for (int j = 0; j < 4; j++)
            #pragma unroll
            for (int c = 0; c < 4; c++) acc[i][j][c] = 0.f;

    const int t8 = lane >> 3;
    const int r8 = lane & 7;
    const uint32_t aoff = (uint32_t)((warpM * 48 + (t8 & 1) * 8 + r8) * PITCHB + (t8 >> 1) * 16);
    const uint32_t boff = (uint32_t)(2 * APLANE_B +
                          (warpN * 32 + (t8 >> 1) * 8 + r8) * PITCHB + (t8 & 1) * 16);

    auto load_tile = [&](int s, int t) {
        const int k0 = t * BK;
        uint32_t stage = sb + (uint32_t)(s * STAGE_B);
        #pragma unroll
        for (int j = 0; j < NCHUNK / 256; j++) {
            int c = tid + j * 256;
            const __nv_bfloat16* g;
            uint32_t sa;
            if (c < 768) {                       // A planes: 2 x 96 rows x 4 chunks
                int pl = c / 384;
                int cc = c - pl * 384;
                int row = cc >> 2, c4 = cc & 3;
                g = (pl == 0 ? Ahi : Alo) + (size_t)(m0 + row) * DIM + k0 + c4 * 8;
                sa = stage + (uint32_t)(pl * APLANE_B + row * PITCHB + c4 * 16);
            } else {                             // B planes: 2 x 128 rows x 4 chunks
                int c2 = c - 768;
                int pl = c2 >> 9;
                int cc = c2 & 511;
                int row = cc >> 2, c4 = cc & 3;
                g = (pl == 0 ? Whi : Wlo) + (size_t)(n0 + row) * DIM + k0 + c4 * 8;
                sa = stage + (uint32_t)(2 * APLANE_B + pl * BPLANE_B + row * PITCHB + c4 * 16);
            }
            cp16(sa, g);
        }
    };

    #pragma unroll
    for (int s = 0; s < STAGES; s++) {
        load_tile(s, s);
        CP_COMMIT();
    }

    for (int t = 0; t < NT_K; t++) {
        CP_WAIT(1);
        __syncthreads();
        uint32_t stg = sb + (uint32_t)((t % STAGES) * STAGE_B);
        uint32_t aB = stg + aoff;
        uint32_t bB = stg + boff;

        #pragma unroll
        for (int kk = 0; kk < BK; kk += 16) {
            uint32_t Ah[3][4], Al[3][4], Bh[4][2], Bl[4][2];
            #pragma unroll
            for (int mi = 0; mi < 3; mi++) {
                uint32_t a = aB + (uint32_t)(mi * 16 * PITCHB + kk * 2);
                ldsm4(Ah[mi], a);
                ldsm4(Al[mi], a + APLANE_B);
            }
            #pragma unroll
            for (int nip = 0; nip < 2; nip++) {
                uint32_t b = bB + (uint32_t)(nip * 16 * PITCHB + kk * 2);
                uint32_t th[4], tl[4];
                ldsm4(th, b);
                ldsm4(tl, b + BPLANE_B);
                Bh[nip * 2][0] = th[0]; Bh[nip * 2][1] = th[1];
                Bh[nip * 2 + 1][0] = th[2]; Bh[nip * 2 + 1][1] = th[3];
                Bl[nip * 2][0] = tl[0]; Bl[nip * 2][1] = tl[1];
                Bl[nip * 2 + 1][0] = tl[2]; Bl[nip * 2 + 1][1] = tl[3];
            }
            #pragma unroll
            for (int mi = 0; mi < 3; mi++)
                #pragma unroll
                for (int ni = 0; ni < 4; ni++) {
                    mma_bf16(acc[mi][ni], Ah[mi], Bh[ni]);
                    mma_bf16(acc[mi][ni], Ah[mi], Bl[ni]);
                    mma_bf16(acc[mi][ni], Al[mi], Bh[ni]);
                }
        }
        __syncthreads();
        if (t + STAGES < NT_K) load_tile(t % STAGES, t + STAGES);
        CP_COMMIT();
    }

    // ---- epilogue ----
    #pragma unroll
    for (int mi = 0; mi < 3; mi++) {
        #pragma unroll
        for (int half = 0; half < 2; half++) {
            size_t m = (size_t)(m0 + warpM * 48 + mi * 16 + gid + half * 8);
            #pragma unroll
            for (int ni = 0; ni < 4; ni++) {
                int n = n0 + warpN * 32 + ni * 8 + 2 * tig;
                float r0 = acc[mi][ni][half * 2 + 0];
                float r1 = acc[mi][ni][half * 2 + 1];
                float2 bs = *(const float2*)(bias + n);
                float2 bb = *(const float2*)(base + m * DIM + n);
                float2 o;
                o.x = bb.x + sign * (r0 + bs.x);
                o.y = bb.y + sign * (r1 + bs.y);
                *(float2*)(outp + m * DIM + n) = o;
                if (emit) {
                    float2 a2 = *(const float2*)(aN + n);
                    float2 c2 = *(const float2*)(cN + n);
                    float s0 = a2.x * o.x + c2.x;
                    float s1 = a2.y * o.y + c2.y;
                    __nv_bfloat162 h2, l2;
                    bf16split(s0, h2.x, l2.x);
                    bf16split(s1, h2.y, l2.y);
                    *(__nv_bfloat162*)(eHi + m * DIM + n) = h2;
                    *(__nv_bfloat162*)(eLo + m * DIM + n) = l2;
                }
            }
        }
    }
}

// ---------------------------------------------------------------------------
extern "C" void kernel_launch(void* const* d_in, const int* in_sizes, int n_in,
                              void* d_out, int out_size)
{
    const float* x   = (const float*)d_in[0];
    const float* W1  = (const float*)d_in[2];
    const float* b1  = (const float*)d_in[3];
    const float* g1  = (const float*)d_in[4];
    const float* be1 = (const float*)d_in[5];
    const float* m1  = (const float*)d_in[6];
    const float* v1  = (const float*)d_in[7];
    const float* W3  = (const float*)d_in[8];
    const float* b3  = (const float*)d_in[9];
    const float* g3  = (const float*)d_in[10];
    const float* be3 = (const float*)d_in[11];
    const float* m3  = (const float*)d_in[12];
    const float* v3  = (const float*)d_in[13];
    const float* kop = (const float*)d_in[14];
    float* out = (float*)d_out;

    float *A, *B, *aF, *cF, *aG, *cG;
    __nv_bfloat16 *H0, *L0, *H1, *L1, *W1h, *W1l, *W3h, *W3l;
    cudaGetSymbolAddress((void**)&A,  g_A);
    cudaGetSymbolAddress((void**)&B,  g_B);
    cudaGetSymbolAddress((void**)&H0, g_H0);
    cudaGetSymbolAddress((void**)&L0, g_L0);
    cudaGetSymbolAddress((void**)&H1, g_H1);
    cudaGetSymbolAddress((void**)&L1, g_L1);
    cudaGetSymbolAddress((void**)&W1h, g_W1Thi);
    cudaGetSymbolAddress((void**)&W1l, g_W1Tlo);
    cudaGetSymbolAddress((void**)&W3h, g_W3Thi);
    cudaGetSymbolAddress((void**)&W3l, g_W3Tlo);
    cudaGetSymbolAddress((void**)&aF, g_aF);
    cudaGetSymbolAddress((void**)&cF, g_cF);
    cudaGetSymbolAddress((void**)&aG, g_aG);
    cudaGetSymbolAddress((void**)&cG, g_cG);

    static int smem_set = 0;
    if (!smem_set) {
        cudaFuncSetAttribute(gemm_tc_kernel, cudaFuncAttributeMaxDynamicSharedMemorySize,
                             SM_TOTAL);
        smem_set = 1;
    }

    dim3 ggrid(DIM / GN, NIMG / GM);           // (16, 32) = 512 CTAs
    const int SPLIT_BLKS = (int)(((size_t)NIMG * DIM / 4 + 255) / 256);
    const int MIX_BLKS   = (int)(((size_t)NIMG * IMGE / 4 + 255) / 256);
    const int FULL_BLKS  = (int)((T_FULL / 4 + 255) / 256);
    dim3 wgrid(DIM / 32, DIM / 32), wblk(32, 8);

    bncoef_kernel<<<8, 256>>>(g1, be1, m1, v1, g3, be3, m3, v3);
    wprep_kernel<<<wgrid, wblk>>>(W1, W1h, W1l);
    wprep_kernel<<<wgrid, wblk>>>(W3, W3h, W3l);

    copyslice_kernel<<<FULL_BLKS, 256>>>(x, out + S0, out + S5);

    // ---- Encoder ----
    split_prep_kernel<<<SPLIT_BLKS, 256>>>(x, A, B, aF, cF, H0, L0, 0);
    gemm_tc_kernel<<<ggrid, 256, SM_TOTAL>>>(H0, L0, W1h, W1l, b1, A, A, +1.0f,
                                             aG, cG, H1, L1, 1);
    gemm_tc_kernel<<<ggrid, 256, SM_TOTAL>>>(H1, L1, W3h, W3l, b3, B, B, +1.0f,
                                             aF, cF, H0, L0, 0);
    mix_kernel<<<MIX_BLKS, 256>>>(A, B, out + S1, out + S6);   // phiX + phiX[:,1:]

    // ---- Decoder(phiX) ----
    split_prep_kernel<<<SPLIT_BLKS, 256>>>(out + S1, A, B, aG, cG, H0, L0, 1);
    gemm_tc_kernel<<<ggrid, 256, SM_TOTAL>>>(H0, L0, W3h, W3l, b3, B, B, -1.0f,
                                             aF, cF, H1, L1, 1);
    gemm_tc_kernel<<<ggrid, 256, SM_TOTAL>>>(H1, L1, W1h, W1l, b1, A, A, -1.0f,
                                             aF, cF, H0, L0, 0);
    mix_kernel<<<MIX_BLKS, 256>>>(A, B, out + S2, nullptr);    // dephiPhiX

    // ---- Koopman ----
    koop_kernel<<<NIMG, 256>>>(out + S1, kop, out + S3);       // kPhix

    // ---- Decoder(kPhix) ----
    split_prep_kernel<<<SPLIT_BLKS, 256>>>(out + S3, A, B, aG, cG, H0, L0, 1);
    gemm_tc_kernel<<<ggrid, 256, SM_TOTAL>>>(H0, L0, W3h, W3l, b3, B, B, -1.0f,
                                             aF, cF, H1, L1, 1);
    gemm_tc_kernel<<<ggrid, 256, SM_TOTAL>>>(H1, L1, W1h, W1l, b1, A, A, -1.0f,
                                             aF, cF, H0, L0, 0);
    mix_kernel<<<MIX_BLKS, 256>>>(A, B, out + S4, nullptr);    // dePhiKPhiX
}

// round 8
// speedup vs baseline: 2.4939x; 1.0129x over previous
#include <cuda_runtime.h>
#include <cuda_bf16.h>
#include <cstdint>

// ---------------------------------------------------------------------------
// Problem constants
// ---------------------------------------------------------------------------
#define CCN   256
#define STD   12
#define FS    64
#define HALF  32
#define NIMG  (CCN*STD)          // 3072
#define DIM   2048               // FS*HALF
#define IMGE  (FS*FS)            // 4096

static const size_t T_FULL  = (size_t)NIMG * IMGE;
static const size_t T_SLICE = (size_t)CCN * 11 * IMGE;

// Output section offsets (floats)
static const size_t S0 = 0;                    // x
static const size_t S1 = S0 + T_FULL;          // phiX
static const size_t S2 = S1 + T_FULL;          // dephiPhiX
static const size_t S3 = S2 + T_FULL;          // kPhix
static const size_t S4 = S3 + T_FULL;          // dePhiKPhiX
static const size_t S5 = S4 + T_FULL;          // x[:,1:]
static const size_t S6 = S5 + T_SLICE;         // phiX[:,1:]

// ---------------------------------------------------------------------------
// Scratch (device globals — no runtime allocation allowed)
// ---------------------------------------------------------------------------
__device__ float         g_A [(size_t)NIMG * DIM];
__device__ float         g_B [(size_t)NIMG * DIM];
__device__ float         g_C [(size_t)NIMG * DIM];
__device__ float         g_D [(size_t)NIMG * DIM];
__device__ __nv_bfloat16 g_H0[(size_t)NIMG * DIM];
__device__ __nv_bfloat16 g_L0[(size_t)NIMG * DIM];
__device__ __nv_bfloat16 g_H1[(size_t)NIMG * DIM];
__device__ __nv_bfloat16 g_L1[(size_t)NIMG * DIM];
__device__ __nv_bfloat16 g_W1Thi[(size_t)DIM * DIM];   // W1^T hi  [N,K]
__device__ __nv_bfloat16 g_W1Tlo[(size_t)DIM * DIM];
__device__ __nv_bfloat16 g_W3Thi[(size_t)DIM * DIM];
__device__ __nv_bfloat16 g_W3Tlo[(size_t)DIM * DIM];
__device__ float g_aF[DIM], g_cF[DIM], g_aG[DIM], g_cG[DIM];

// ---------------------------------------------------------------------------
// Helpers (base sm_103 target only — NO tcgen05 / arch-'a' features)
// ---------------------------------------------------------------------------
__device__ __forceinline__ uint32_t smem_u32(const void* p) {
    uint32_t a;
    asm("{ .reg .u64 t; cvta.to.shared.u64 t, %1; cvt.u32.u64 %0, t; }" : "=r"(a) : "l"(p));
    return a;
}

__device__ __forceinline__ void cp16(uint32_t saddr, const void* gptr) {
    asm volatile("cp.async.cg.shared.global [%0], [%1], 16;" :: "r"(saddr), "l"(gptr));
}
#define CP_COMMIT() asm volatile("cp.async.commit_group;" ::: "memory")
#define CP_WAIT(n)  asm volatile("cp.async.wait_group %0;" :: "n"(n) : "memory")

__device__ __forceinline__ void ldsm4(uint32_t* r, uint32_t addr) {
    asm volatile("ldmatrix.sync.aligned.m8n8.x4.shared.b16 {%0,%1,%2,%3}, [%4];"
                 : "=r"(r[0]), "=r"(r[1]), "=r"(r[2]), "=r"(r[3]) : "r"(addr));
}

__device__ __forceinline__ void mma_bf16(float* d, const uint32_t* a, const uint32_t* b) {
    asm volatile(
        "mma.sync.aligned.m16n8k16.row.col.f32.bf16.bf16.f32 "
        "{%0,%1,%2,%3}, {%4,%5,%6,%7}, {%8,%9}, {%0,%1,%2,%3};"
        : "+f"(d[0]), "+f"(d[1]), "+f"(d[2]), "+f"(d[3])
        : "r"(a[0]), "r"(a[1]), "r"(a[2]), "r"(a[3]), "r"(b[0]), "r"(b[1]));
}

__device__ __forceinline__ void bf16split(float s, __nv_bfloat16& h, __nv_bfloat16& l) {
    h = __float2bfloat16(s);
    l = __float2bfloat16(s - __bfloat162float(h));
}

// quantize 4 BN'd values into packed bf16 hi/lo uint2
__device__ __forceinline__ void quad_quant(const float* s, uint2& hv, uint2& lv) {
    __nv_bfloat162 h01, l01, h23, l23;
    bf16split(s[0], h01.x, l01.x); bf16split(s[1], h01.y, l01.y);
    bf16split(s[2], h23.x, l23.x); bf16split(s[3], h23.y, l23.y);
    hv.x = *(uint32_t*)&h01; hv.y = *(uint32_t*)&h23;
    lv.x = *(uint32_t*)&l01; lv.y = *(uint32_t*)&l23;
}

// ---------------------------------------------------------------------------
// BN coefficient precompute
// ---------------------------------------------------------------------------
__global__ void bncoef_kernel(const float* __restrict__ g1, const float* __restrict__ be1,
                              const float* __restrict__ m1, const float* __restrict__ v1,
                              const float* __restrict__ g3, const float* __restrict__ be3,
                              const float* __restrict__ m3, const float* __restrict__ v3)
{
    int k = blockIdx.x * blockDim.x + threadIdx.x;
    if (k < DIM) {
        float aF = g1[k] * rsqrtf(v1[k] + 1e-3f);
        g_aF[k] = aF;  g_cF[k] = be1[k] - aF * m1[k];
        float aG = g3[k] * rsqrtf(v3[k] + 1e-3f);
        g_aG[k] = aG;  g_cG[k] = be3[k] - aG * m3[k];
    }
}

// ---------------------------------------------------------------------------
// Weight prep: W [K,N] -> W^T [N,K] split into bf16 hi/lo planes
// ---------------------------------------------------------------------------
__global__ void wprep_kernel(const float* __restrict__ W, __nv_bfloat16* __restrict__ Thi,
                             __nv_bfloat16* __restrict__ Tlo)
{
    __shared__ float t[32][33];
    int bn = blockIdx.x * 32;
    int bk = blockIdx.y * 32;
    int tx = threadIdx.x, ty = threadIdx.y;   // 32 x 8
    #pragma unroll
    for (int i = 0; i < 32; i += 8)
        t[ty + i][tx] = W[(size_t)(bk + ty + i) * DIM + bn + tx];
    __syncthreads();
    #pragma unroll
    for (int i = 0; i < 32; i += 8) {
        float v = t[tx][ty + i];
        size_t o = (size_t)(bn + ty + i) * DIM + bk + tx;
        __nv_bfloat16 h, l;
        bf16split(v, h, l);
        Thi[o] = h;
        Tlo[o] = l;
    }
}

// ---------------------------------------------------------------------------
// xprep: one pass over x -> {S0 copy, S5 slice, u1, u2, BN_F(u2) hi/lo planes}
// Thread owns one u-space quad (n, i, j0..j0+3) == x cols 2j0..2j0+7.
// ---------------------------------------------------------------------------
__global__ void xprep_kernel(const float* __restrict__ x, float* __restrict__ dst,
                             float* __restrict__ dsl,
                             float* __restrict__ u1, float* __restrict__ u2,
                             const float* __restrict__ aC, const float* __restrict__ cC,
                             __nv_bfloat16* __restrict__ hi, __nv_bfloat16* __restrict__ lo)
{
    size_t q = (size_t)blockIdx.x * blockDim.x + threadIdx.x;
    if (q >= (size_t)NIMG * DIM / 4) return;
    size_t idx = q * 4;
    int n = (int)(idx >> 11);
    int i = (int)((idx >> 5) & 63);
    int j0 = (int)(idx & 31);
    int p = i & 1;
    size_t xoff = ((size_t)n << 12) + ((size_t)i << 6) + (j0 << 1);
    float4 a = *(const float4*)(x + xoff);
    float4 b = *(const float4*)(x + xoff + 4);
    // copy + slice
    *(float4*)(dst + xoff) = a;
    *(float4*)(dst + xoff + 4) = b;
    int s = n % STD;
    if (s >= 1) {
        int cc = n / STD;
        size_t so = ((size_t)(cc * 11 + s - 1) << 12) + ((size_t)i << 6) + (j0 << 1);
        *(float4*)(dsl + so) = a;
        *(float4*)(dsl + so + 4) = b;
    }
    float4 f1, f2;
    if (p == 0) { f1 = make_float4(a.x, a.z, b.x, b.z); f2 = make_float4(a.y, a.w, b.y, b.w); }
    else        { f1 = make_float4(a.y, a.w, b.y, b.w); f2 = make_float4(a.x, a.z, b.x, b.z); }
    *(float4*)(u1 + idx) = f1;
    *(float4*)(u2 + idx) = f2;
    int k = (int)(idx & 2047);
    float4 av = *(const float4*)(aC + k);
    float4 cv = *(const float4*)(cC + k);
    float sv[4] = { av.x * f2.x + cv.x, av.y * f2.y + cv.y,
                    av.z * f2.z + cv.z, av.w * f2.w + cv.w };
    uint2 hv, lv;
    quad_quant(sv, hv, lv);
    *(uint2*)(hi + idx) = hv;
    *(uint2*)(lo + idx) = lv;
}

// ---------------------------------------------------------------------------
// mixsplit: mix(v1,w2) -> y (+slice), AND emit split(y)=(w1,w2) + BN(w1) planes.
// Identity used: split(mix(v1,w2)): even rows (u1,u2)=(v1,w2);
// odd rows u1[j]=v1[(j+1)%32], u2[j]=w2[(j-1)%32].
// y[i,2j+p]=u1[j], y[i,2j+1-p]=u2[j].
// Writes u planes to DIFFERENT buffers (no in-place permutation race).
// ---------------------------------------------------------------------------
__global__ void mixsplit_kernel(const float* __restrict__ v1b, const float* __restrict__ w2b,
                                float* __restrict__ y, float* __restrict__ ysl,
                                float* __restrict__ u1o, float* __restrict__ u2o,
                                const float* __restrict__ aC, const float* __restrict__ cC,
                                __nv_bfloat16* __restrict__ hi, __nv_bfloat16* __restrict__ lo)
{
    size_t q = (size_t)blockIdx.x * blockDim.x + threadIdx.x;
    if (q >= (size_t)NIMG * DIM / 4) return;
    size_t idx = q * 4;
    int n = (int)(idx >> 11);
    int i = (int)((idx >> 5) & 63);
    int j0 = (int)(idx & 31);
    int p = i & 1;
    const float* v1 = v1b + ((size_t)n << 11) + ((size_t)i << 5);
    const float* w2 = w2b + ((size_t)n << 11) + ((size_t)i << 5);
    float u1[4], u2[4];
    if (p == 0) {
        float4 a = *(const float4*)(v1 + j0);
        float4 b = *(const float4*)(w2 + j0);
        u1[0] = a.x; u1[1] = a.y; u1[2] = a.z; u1[3] = a.w;
        u2[0] = b.x; u2[1] = b.y; u2[2] = b.z; u2[3] = b.w;
    } else {
        #pragma unroll
        for (int t = 0; t < 4; t++) {
            u1[t] = v1[(j0 + t + 1) & 31];
            u2[t] = w2[(j0 + t + 31) & 31];
        }
    }
    *(float4*)(u1o + idx) = make_float4(u1[0], u1[1], u1[2], u1[3]);
    *(float4*)(u2o + idx) = make_float4(u2[0], u2[1], u2[2], u2[3]);
    // BN + quant on u1 (decoder prep)
    int k = (int)(idx & 2047);
    float4 av = *(const float4*)(aC + k);
    float4 cv = *(const float4*)(cC + k);
    float sv[4] = { av.x * u1[0] + cv.x, av.y * u1[1] + cv.y,
                    av.z * u1[2] + cv.z, av.w * u1[3] + cv.w };
    uint2 hv, lv;
    quad_quant(sv, hv, lv);
    *(uint2*)(hi + idx) = hv;
    *(uint2*)(lo + idx) = lv;
    // y: columns 2j0..2j0+7 of row i
    float4 y0, y1;
    if (p == 0) {
        y0 = make_float4(u1[0], u2[0], u1[1], u2[1]);
        y1 = make_float4(u1[2], u2[2], u1[3], u2[3]);
    } else {
        y0 = make_float4(u2[0], u1[0], u2[1], u1[1]);
        y1 = make_float4(u2[2], u1[2], u2[3], u1[3]);
    }
    size_t yoff = ((size_t)n << 12) + ((size_t)i << 6) + (j0 << 1);
    *(float4*)(y + yoff) = y0;
    *(float4*)(y + yoff + 4) = y1;
    if (ysl) {
        int s = n % STD;
        if (s >= 1) {
            int cc = n / STD;
            size_t so = ((size_t)(cc * 11 + s - 1) << 12) + ((size_t)i << 6) + (j0 << 1);
            *(float4*)(ysl + so) = y0;
            *(float4*)(ysl + so + 4) = y1;
        }
    }
}

// ---------------------------------------------------------------------------
// Plain mix (final outputs S2/S4) — float4 stores
// ---------------------------------------------------------------------------
__global__ void mix_kernel(const float* __restrict__ v1b, const float* __restrict__ w2b,
                           float* __restrict__ y)
{
    size_t q = (size_t)blockIdx.x * blockDim.x + threadIdx.x;
    if (q >= (size_t)NIMG * IMGE / 4) return;
    size_t idx = q * 4;
    int n = (int)(idx >> 12);
    int r = (int)((idx >> 6) & 63);
    int c0 = (int)(idx & 63);
    int h = c0 >> 1;
    const float* v1 = v1b + ((size_t)n << 11) + ((size_t)r << 5);
    const float* w2 = w2b + ((size_t)n << 11) + ((size_t)r << 5);
    float4 o;
    if ((r & 1) == 0) {
        float2 vv = *(const float2*)(v1 + h);
        float2 ww = *(const float2*)(w2 + h);
        o = make_float4(vv.x, ww.x, vv.y, ww.y);
    } else {
        o.x = w2[(h + 31) & 31];
        o.y = v1[(h + 1) & 31];
        o.z = w2[h];
        o.w = v1[(h + 2) & 31];
    }
    *(float4*)(y + idx) = o;
}

// ---------------------------------------------------------------------------
// Koopman step + fused split/BN-quant of the result.
// 64x64 @ 64x64 per block; result staged into smem (reusing si) for the split.
// ---------------------------------------------------------------------------
__global__ void __launch_bounds__(256)
koop_kernel(const float* __restrict__ phi, const float* __restrict__ kop,
            float* __restrict__ outk,
            float* __restrict__ u1o, float* __restrict__ u2o,
            const float* __restrict__ aC, const float* __restrict__ cC,
            __nv_bfloat16* __restrict__ hi, __nv_bfloat16* __restrict__ lo)
{
    __shared__ float sk[64 * 64];
    __shared__ float si[64 * 68];     // image (transposed), later reused as y rows
    int m = blockIdx.x;
    int nprime = m / STD, s = m % STD;
    int q = nprime >> 2, b = nprime & 3;
    int nin = b * 64 + q;
    const float* src = phi + (size_t)(nin * STD + s) * IMGE;
    float* dst = outk + (size_t)m * IMGE;
    int t = threadIdx.x;

    #pragma unroll
    for (int e = t * 4; e < IMGE; e += 1024)
        *(float4*)(sk + e) = *(const float4*)(kop + e);
    #pragma unroll
    for (int e = t; e < IMGE; e += 256) {
        int i = e >> 6, j = e & 63;
        si[j * 68 + i] = src[e];
    }
    __syncthreads();

    int tr = t >> 4, tc = t & 15;
    float acc[4][4];
    #pragma unroll
    for (int a = 0; a < 4; a++)
        #pragma unroll
        for (int bb = 0; bb < 4; bb++) acc[a][bb] = 0.f;

    const float* siP = si + tr * 4;
    const float* skP = sk + tc * 4;
    #pragma unroll 4
    for (int j = 0; j < 64; j++) {
        float4 av = *(const float4*)(siP + j * 68);
        float4 bv = *(const float4*)(skP + j * 64);
        acc[0][0] += av.x * bv.x; acc[0][1] += av.x * bv.y;
        acc[0][2] += av.x * bv.z; acc[0][3] += av.x * bv.w;
        acc[1][0] += av.y * bv.x; acc[1][1] += av.y * bv.y;
        acc[1][2] += av.y * bv.z; acc[1][3] += av.y * bv.w;
        acc[2][0] += av.z * bv.x; acc[2][1] += av.z * bv.y;
        acc[2][2] += av.z * bv.z; acc[2][3] += av.z * bv.w;
        acc[3][0] += av.w * bv.x; acc[3][1] += av.w * bv.y;
        acc[3][2] += av.w * bv.z; acc[3][3] += av.w * bv.w;
    }
    __syncthreads();                  // all si reads done; reuse si as y buffer
    float* sy = si;                   // row-major, pitch 66
    #pragma unroll
    for (int dr = 0; dr < 4; dr++) {
        int row = tr * 4 + dr;
        float4 o = make_float4(acc[dr][0], acc[dr][1], acc[dr][2], acc[dr][3]);
        *(float4*)(dst + row * 64 + tc * 4) = o;
        sy[row * 66 + tc * 4 + 0] = o.x;
        sy[row * 66 + tc * 4 + 1] = o.y;
        sy[row * 66 + tc * 4 + 2] = o.z;
        sy[row * 66 + tc * 4 + 3] = o.w;
    }
    __syncthreads();

    // split + BN-quant from smem: 2048 u-elements, 8 per thread
    #pragma unroll
    for (int e8 = 0; e8 < 8; e8++) {
        int e = t + e8 * 256;
        int i = e >> 5, j = e & 31, p = i & 1;
        float uu1 = sy[i * 66 + 2 * j + p];
        float uu2 = sy[i * 66 + 2 * j + 1 - p];
        size_t go = (size_t)m * DIM + e;
        u1o[go] = uu1;
        u2o[go] = uu2;
        float sv = aC[e] * uu1 + cC[e];
        __nv_bfloat16 hq, lq;
        bf16split(sv, hq, lq);
        hi[go] = hq;
        lo[go] = lq;
    }
}

// ---------------------------------------------------------------------------
// BF16x3 mma.sync GEMM (m16n8k16 + ldmatrix) — R6 measured-best config.
// CTA tile 128x128, BK=32, 8 warps (2x4), warp tile 64x32.
// 2-stage cp.async pipeline, 80KB smem -> 2 CTAs per SM.
// ---------------------------------------------------------------------------
#define GM 128
#define GN 128
#define BK 32
#define NT_K (DIM / BK)            // 64
#define PITCHB 80
#define PLANE_B (128 * PITCHB)     // 10240
#define STAGE_B (4 * PLANE_B)      // 40960
#define STAGES 2
#define SM_TOTAL (STAGES * STAGE_B)   // 81920

__global__ void __launch_bounds__(256, 2)
gemm_tc_kernel(const __nv_bfloat16* __restrict__ Ahi, const __nv_bfloat16* __restrict__ Alo,
               const __nv_bfloat16* __restrict__ Whi, const __nv_bfloat16* __restrict__ Wlo,
               const float* __restrict__ bias, const float* base, float* outp, float sign,
               const float* __restrict__ aN, const float* __restrict__ cN,
               __nv_bfloat16* eHi, __nv_bfloat16* eLo, int emit)
{
    extern __shared__ char smem[];
    uint32_t sb = smem_u32(smem);
    const int tid  = threadIdx.x;
    const int wid  = tid >> 5;
    const int lane = tid & 31;
    const int gid  = lane >> 2;
    const int tig  = lane & 3;
    const int warpM = wid >> 2;
    const int warpN = wid & 3;
    const int m0 = blockIdx.y * GM;
    const int n0 = blockIdx.x * GN;

    float acc[4][4][4];
    #pragma unroll
    for (int i = 0; i < 4; i++)
        #pragma unroll
        for (int j = 0; j < 4; j++)
            #pragma unroll
            for (int c = 0; c < 4; c++) acc[i][j][c] = 0.f;

    const int t8 = lane >> 3;
    const int r8 = lane & 7;
    const uint32_t aoff = (uint32_t)((warpM * 64 + (t8 & 1) * 8 + r8) * PITCHB + (t8 >> 1) * 16);
    const uint32_t boff = (uint32_t)(2 * PLANE_B +
                          (warpN * 32 + (t8 >> 1) * 8 + r8) * PITCHB + (t8 & 1) * 16);

    auto load_tile = [&](int s, int t) {
        const int k0 = t * BK;
        uint32_t stage = sb + (uint32_t)(s * STAGE_B);
        #pragma unroll
        for (int j = 0; j < 8; j++) {
            int c = tid + j * 256;
            int pl = c >> 9;
            int cc = c & 511;
            int row = cc >> 2;
            int c4  = cc & 3;
            const __nv_bfloat16* g;
            if (pl == 0)      g = Ahi + (size_t)(m0 + row) * DIM + k0 + c4 * 8;
            else if (pl == 1) g = Alo + (size_t)(m0 + row) * DIM + k0 + c4 * 8;
            else if (pl == 2) g = Whi + (size_t)(n0 + row) * DIM + k0 + c4 * 8;
            else              g = Wlo + (size_t)(n0 + row) * DIM + k0 + c4 * 8;
            cp16(stage + (uint32_t)(pl * PLANE_B + row * PITCHB + c4 * 16), g);
        }
    };

    #pragma unroll
    for (int s = 0; s < STAGES; s++) {
        load_tile(s, s);
        CP_COMMIT();
    }

    for (int t = 0; t < NT_K; t++) {
        CP_WAIT(1);
        __syncthreads();
        uint32_t stg = sb + (uint32_t)((t % STAGES) * STAGE_B);
        uint32_t aB = stg + aoff;
        uint32_t bB = stg + boff;

        #pragma unroll
        for (int kk = 0; kk < BK; kk += 16) {
            uint32_t Ah[4][4], Al[4][4], Bh[4][2], Bl[4][2];
            #pragma unroll
            for (int mi = 0; mi < 4; mi++) {
                uint32_t a = aB + (uint32_t)(mi * 16 * PITCHB + kk * 2);
                ldsm4(Ah[mi], a);
                ldsm4(Al[mi], a + PLANE_B);
            }
            #pragma unroll
            for (int nip = 0; nip < 2; nip++) {
                uint32_t b = bB + (uint32_t)(nip * 16 * PITCHB + kk * 2);
                uint32_t th[4], tl[4];
                ldsm4(th, b);
                ldsm4(tl, b + PLANE_B);
                Bh[nip * 2][0] = th[0]; Bh[nip * 2][1] = th[1];
                Bh[nip * 2 + 1][0] = th[2]; Bh[nip * 2 + 1][1] = th[3];
                Bl[nip * 2][0] = tl[0]; Bl[nip * 2][1] = tl[1];
                Bl[nip * 2 + 1][0] = tl[2]; Bl[nip * 2 + 1][1] = tl[3];
            }
            #pragma unroll
            for (int mi = 0; mi < 4; mi++)
                #pragma unroll
                for (int ni = 0; ni < 4; ni++) {
                    mma_bf16(acc[mi][ni], Ah[mi], Bh[ni]);
                    mma_bf16(acc[mi][ni], Ah[mi], Bl[ni]);
                    mma_bf16(acc[mi][ni], Al[mi], Bh[ni]);
                }
        }
        __syncthreads();
        if (t + STAGES < NT_K) load_tile(t % STAGES, t + STAGES);
        CP_COMMIT();
    }

    // ---- epilogue ----
    #pragma unroll
    for (int mi = 0; mi < 4; mi++) {
        #pragma unroll
        for (int half = 0; half < 2; half++) {
            size_t m = (size_t)(m0 + warpM * 64 + mi * 16 + gid + half * 8);
            #pragma unroll
            for (int ni = 0; ni < 4; ni++) {
                int n = n0 + warpN * 32 + ni * 8 + 2 * tig;
                float r0 = acc[mi][ni][half * 2 + 0];
                float r1 = acc[mi][ni][half * 2 + 1];
                float2 bs = *(const float2*)(bias + n);
                float2 bb = *(const float2*)(base + m * DIM + n);
                float2 o;
                o.x = bb.x + sign * (r0 + bs.x);
                o.y = bb.y + sign * (r1 + bs.y);
                *(float2*)(outp + m * DIM + n) = o;
                if (emit) {
                    float2 a2 = *(const float2*)(aN + n);
                    float2 c2 = *(const float2*)(cN + n);
                    float s0 = a2.x * o.x + c2.x;
                    float s1 = a2.y * o.y + c2.y;
                    __nv_bfloat162 h2, l2;
                    bf16split(s0, h2.x, l2.x);
                    bf16split(s1, h2.y, l2.y);
                    *(__nv_bfloat162*)(eHi + m * DIM + n) = h2;
                    *(__nv_bfloat162*)(eLo + m * DIM + n) = l2;
                }
            }
        }
    }
}

// ---------------------------------------------------------------------------
extern "C" void kernel_launch(void* const* d_in, const int* in_sizes, int n_in,
                              void* d_out, int out_size)
{
    const float* x   = (const float*)d_in[0];
    const float* W1  = (const float*)d_in[2];
    const float* b1  = (const float*)d_in[3];
    const float* g1  = (const float*)d_in[4];
    const float* be1 = (const float*)d_in[5];
    const float* m1  = (const float*)d_in[6];
    const float* v1  = (const float*)d_in[7];
    const float* W3  = (const float*)d_in[8];
    const float* b3  = (const float*)d_in[9];
    const float* g3  = (const float*)d_in[10];
    const float* be3 = (const float*)d_in[11];
    const float* m3  = (const float*)d_in[12];
    const float* v3  = (const float*)d_in[13];
    const float* kop = (const float*)d_in[14];
    float* out = (float*)d_out;

    float *A, *B, *C, *D, *aF, *cF, *aG, *cG;
    __nv_bfloat16 *H0, *L0, *H1, *L1, *W1h, *W1l, *W3h, *W3l;
    cudaGetSymbolAddress((void**)&A,  g_A);
    cudaGetSymbolAddress((void**)&B,  g_B);
    cudaGetSymbolAddress((void**)&C,  g_C);
    cudaGetSymbolAddress((void**)&D,  g_D);
    cudaGetSymbolAddress((void**)&H0, g_H0);
    cudaGetSymbolAddress((void**)&L0, g_L0);
    cudaGetSymbolAddress((void**)&H1, g_H1);
    cudaGetSymbolAddress((void**)&L1, g_L1);
    cudaGetSymbolAddress((void**)&W1h, g_W1Thi);
    cudaGetSymbolAddress((void**)&W1l, g_W1Tlo);
    cudaGetSymbolAddress((void**)&W3h, g_W3Thi);
    cudaGetSymbolAddress((void**)&W3l, g_W3Tlo);
    cudaGetSymbolAddress((void**)&aF, g_aF);
    cudaGetSymbolAddress((void**)&cF, g_cF);
    cudaGetSymbolAddress((void**)&aG, g_aG);
    cudaGetSymbolAddress((void**)&cG, g_cG);

    static int smem_set = 0;
    if (!smem_set) {
        cudaFuncSetAttribute(gemm_tc_kernel, cudaFuncAttributeMaxDynamicSharedMemorySize,
                             SM_TOTAL);
        smem_set = 1;
    }

    dim3 ggrid(DIM / GN, NIMG / GM);           // (16, 24)
    const int UQ_BLKS  = (int)(((size_t)NIMG * DIM / 4 + 255) / 256);
    const int MIX_BLKS = (int)(((size_t)NIMG * IMGE / 4 + 255) / 256);
    dim3 wgrid(DIM / 32, DIM / 32), wblk(32, 8);

    bncoef_kernel<<<8, 256>>>(g1, be1, m1, v1, g3, be3, m3, v3);
    wprep_kernel<<<wgrid, wblk>>>(W1, W1h, W1l);
    wprep_kernel<<<wgrid, wblk>>>(W3, W3h, W3l);

    // ---- x prep: S0, S5, u1(A), u2(B), BN_F(u2) planes, one read of x ----
    xprep_kernel<<<UQ_BLKS, 256>>>(x, out + S0, out + S5, A, B, aF, cF, H0, L0);

    // ---- Encoder ----
    gemm_tc_kernel<<<ggrid, 256, SM_TOTAL>>>(H0, L0, W1h, W1l, b1, A, A, +1.0f,
                                             aG, cG, H1, L1, 1);          // A = v1
    gemm_tc_kernel<<<ggrid, 256, SM_TOTAL>>>(H1, L1, W3h, W3l, b3, B, B, +1.0f,
                                             aF, cF, H0, L0, 0);          // B = w2
    // phiX + slice + decoder split (C=w1, D=w2) + BN_G(w1) planes
    mixsplit_kernel<<<UQ_BLKS, 256>>>(A, B, out + S1, out + S6, C, D, aG, cG, H0, L0);

    // ---- Decoder(phiX) ----
    gemm_tc_kernel<<<ggrid, 256, SM_TOTAL>>>(H0, L0, W3h, W3l, b3, D, D, -1.0f,
                                             aF, cF, H1, L1, 1);          // D = v2
    gemm_tc_kernel<<<ggrid, 256, SM_TOTAL>>>(H1, L1, W1h, W1l, b1, C, C, -1.0f,
                                             aF, cF, H0, L0, 0);          // C = u1
    mix_kernel<<<MIX_BLKS, 256>>>(C, D, out + S2);                        // dephiPhiX

    // ---- Koopman (+ fused split of kPhix: A=w1', B=w2', BN_G(w1') planes) ----
    koop_kernel<<<NIMG, 256>>>(out + S1, kop, out + S3, A, B, aG, cG, H0, L0);

    // ---- Decoder(kPhix) ----
    gemm_tc_kernel<<<ggrid, 256, SM_TOTAL>>>(H0, L0, W3h, W3l, b3, B, B, -1.0f,
                                             aF, cF, H1, L1, 1);          // B = v2'
    gemm_tc_kernel<<<ggrid, 256, SM_TOTAL>>>(H1, L1, W1h, W1l, b1, A, A, -1.0f,
                                             aF, cF, H0, L0, 0);          // A = u1'
    mix_kernel<<<MIX_BLKS, 256>>>(A, B, out + S4);                        // dePhiKPhiX
}

// round 9
// speedup vs baseline: 3.5497x; 1.4234x over previous
#include <cuda_runtime.h>
#include <cuda_bf16.h>
#include <cuda_fp16.h>
#include <cstdint>

// ---------------------------------------------------------------------------
// Problem constants
// ---------------------------------------------------------------------------
#define CCN   256
#define STD   12
#define FS    64
#define HALF  32
#define NIMG  (CCN*STD)          // 3072
#define DIM   2048               // FS*HALF
#define IMGE  (FS*FS)            // 4096

#define WSCALE     64.0f
#define WSCALE_INV 0.015625f

static const size_t T_FULL  = (size_t)NIMG * IMGE;
static const size_t T_SLICE = (size_t)CCN * 11 * IMGE;

// Output section offsets (floats)
static const size_t S0 = 0;                    // x
static const size_t S1 = S0 + T_FULL;          // phiX
static const size_t S2 = S1 + T_FULL;          // dephiPhiX
static const size_t S3 = S2 + T_FULL;          // kPhix
static const size_t S4 = S3 + T_FULL;          // dePhiKPhiX
static const size_t S5 = S4 + T_FULL;          // x[:,1:]
static const size_t S6 = S5 + T_SLICE;         // phiX[:,1:]

// ---------------------------------------------------------------------------
// Scratch (device globals — no runtime allocation allowed)
// ---------------------------------------------------------------------------
__device__ float  g_A [(size_t)NIMG * DIM];
__device__ float  g_B [(size_t)NIMG * DIM];
__device__ float  g_C [(size_t)NIMG * DIM];
__device__ float  g_D [(size_t)NIMG * DIM];
__device__ __half g_H0[(size_t)NIMG * DIM];    // fp16 activation plane (ping)
__device__ __half g_H1[(size_t)NIMG * DIM];    // fp16 activation plane (pong)
__device__ __half g_W1Thi[(size_t)DIM * DIM];  // (64*W1)^T hi  [N,K]
__device__ __half g_W1Tlo[(size_t)DIM * DIM];
__device__ __half g_W3Thi[(size_t)DIM * DIM];
__device__ __half g_W3Tlo[(size_t)DIM * DIM];
__device__ float g_aF[DIM], g_cF[DIM], g_aG[DIM], g_cG[DIM];

// ---------------------------------------------------------------------------
// Helpers (base sm_103 target only — NO tcgen05 / arch-'a' features)
// ---------------------------------------------------------------------------
__device__ __forceinline__ uint32_t smem_u32(const void* p) {
    uint32_t a;
    asm("{ .reg .u64 t; cvta.to.shared.u64 t, %1; cvt.u32.u64 %0, t; }" : "=r"(a) : "l"(p));
    return a;
}

__device__ __forceinline__ void cp16(uint32_t saddr, const void* gptr) {
    asm volatile("cp.async.cg.shared.global [%0], [%1], 16;" :: "r"(saddr), "l"(gptr));
}
#define CP_COMMIT() asm volatile("cp.async.commit_group;" ::: "memory")
#define CP_WAIT(n)  asm volatile("cp.async.wait_group %0;" :: "n"(n) : "memory")

__device__ __forceinline__ void ldsm4(uint32_t* r, uint32_t addr) {
    asm volatile("ldmatrix.sync.aligned.m8n8.x4.shared.b16 {%0,%1,%2,%3}, [%4];"
                 : "=r"(r[0]), "=r"(r[1]), "=r"(r[2]), "=r"(r[3]) : "r"(addr));
}

__device__ __forceinline__ void mma_f16(float* d, const uint32_t* a, const uint32_t* b) {
    asm volatile(
        "mma.sync.aligned.m16n8k16.row.col.f32.f16.f16.f32 "
        "{%0,%1,%2,%3}, {%4,%5,%6,%7}, {%8,%9}, {%0,%1,%2,%3};"
        : "+f"(d[0]), "+f"(d[1]), "+f"(d[2]), "+f"(d[3])
        : "r"(a[0]), "r"(a[1]), "r"(a[2]), "r"(a[3]), "r"(b[0]), "r"(b[1]));
}

// pack 4 floats into 4 fp16 (uint2)
__device__ __forceinline__ uint2 quad_h(float s0, float s1, float s2, float s3) {
    __half2 h01 = __floats2half2_rn(s0, s1);
    __half2 h23 = __floats2half2_rn(s2, s3);
    uint2 r;
    r.x = *(uint32_t*)&h01;
    r.y = *(uint32_t*)&h23;
    return r;
}

// ---------------------------------------------------------------------------
// BN coefficient precompute
// ---------------------------------------------------------------------------
__global__ void bncoef_kernel(const float* __restrict__ g1, const float* __restrict__ be1,
                              const float* __restrict__ m1, const float* __restrict__ v1,
                              const float* __restrict__ g3, const float* __restrict__ be3,
                              const float* __restrict__ m3, const float* __restrict__ v3)
{
    int k = blockIdx.x * blockDim.x + threadIdx.x;
    if (k < DIM) {
        float aF = g1[k] * rsqrtf(v1[k] + 1e-3f);
        g_aF[k] = aF;  g_cF[k] = be1[k] - aF * m1[k];
        float aG = g3[k] * rsqrtf(v3[k] + 1e-3f);
        g_aG[k] = aG;  g_cG[k] = be3[k] - aG * m3[k];
    }
}

// ---------------------------------------------------------------------------
// Weight prep: W [K,N] -> (64*W)^T [N,K] split into fp16 hi/lo planes
// ---------------------------------------------------------------------------
__global__ void wprep_kernel(const float* __restrict__ W, __half* __restrict__ Thi,
                             __half* __restrict__ Tlo)
{
    __shared__ float t[32][33];
    int bn = blockIdx.x * 32;
    int bk = blockIdx.y * 32;
    int tx = threadIdx.x, ty = threadIdx.y;   // 32 x 8
    #pragma unroll
    for (int i = 0; i < 32; i += 8)
        t[ty + i][tx] = W[(size_t)(bk + ty + i) * DIM + bn + tx];
    __syncthreads();
    #pragma unroll
    for (int i = 0; i < 32; i += 8) {
        float v = t[tx][ty + i] * WSCALE;
        size_t o = (size_t)(bn + ty + i) * DIM + bk + tx;
        __half h = __float2half_rn(v);
        __half l = __float2half_rn(v - __half2float(h));
        Thi[o] = h;
        Tlo[o] = l;
    }
}

// ---------------------------------------------------------------------------
// xprep: one pass over x -> {S0 copy, S5 slice, u1, u2, fp16 BN_F(u2) plane}
// ---------------------------------------------------------------------------
__global__ void xprep_kernel(const float* __restrict__ x, float* __restrict__ dst,
                             float* __restrict__ dsl,
                             float* __restrict__ u1, float* __restrict__ u2,
                             const float* __restrict__ aC, const float* __restrict__ cC,
                             __half* __restrict__ hi)
{
    size_t q = (size_t)blockIdx.x * blockDim.x + threadIdx.x;
    if (q >= (size_t)NIMG * DIM / 4) return;
    size_t idx = q * 4;
    int n = (int)(idx >> 11);
    int i = (int)((idx >> 5) & 63);
    int j0 = (int)(idx & 31);
    int p = i & 1;
    size_t xoff = ((size_t)n << 12) + ((size_t)i << 6) + (j0 << 1);
    float4 a = *(const float4*)(x + xoff);
    float4 b = *(const float4*)(x + xoff + 4);
    *(float4*)(dst + xoff) = a;
    *(float4*)(dst + xoff + 4) = b;
    int s = n % STD;
    if (s >= 1) {
        int cc = n / STD;
        size_t so = ((size_t)(cc * 11 + s - 1) << 12) + ((size_t)i << 6) + (j0 << 1);
        *(float4*)(dsl + so) = a;
        *(float4*)(dsl + so + 4) = b;
    }
    float4 f1, f2;
    if (p == 0) { f1 = make_float4(a.x, a.z, b.x, b.z); f2 = make_float4(a.y, a.w, b.y, b.w); }
    else        { f1 = make_float4(a.y, a.w, b.y, b.w); f2 = make_float4(a.x, a.z, b.x, b.z); }
    *(float4*)(u1 + idx) = f1;
    *(float4*)(u2 + idx) = f2;
    int k = (int)(idx & 2047);
    float4 av = *(const float4*)(aC + k);
    float4 cv = *(const float4*)(cC + k);
    *(uint2*)(hi + idx) = quad_h(av.x * f2.x + cv.x, av.y * f2.y + cv.y,
                                 av.z * f2.z + cv.z, av.w * f2.w + cv.w);
}

// ---------------------------------------------------------------------------
// mixsplit: mix(v1,w2) -> y (+slice), AND emit split(y)=(w1,w2) + fp16 BN(w1).
// ---------------------------------------------------------------------------
__global__ void mixsplit_kernel(const float* __restrict__ v1b, const float* __restrict__ w2b,
                                float* __restrict__ y, float* __restrict__ ysl,
                                float* __restrict__ u1o, float* __restrict__ u2o,
                                const float* __restrict__ aC, const float* __restrict__ cC,
                                __half* __restrict__ hi)
{
    size_t q = (size_t)blockIdx.x * blockDim.x + threadIdx.x;
    if (q >= (size_t)NIMG * DIM / 4) return;
    size_t idx = q * 4;
    int n = (int)(idx >> 11);
    int i = (int)((idx >> 5) & 63);
    int j0 = (int)(idx & 31);
    int p = i & 1;
    const float* v1 = v1b + ((size_t)n << 11) + ((size_t)i << 5);
    const float* w2 = w2b + ((size_t)n << 11) + ((size_t)i << 5);
    float u1[4], u2[4];
    if (p == 0) {
        float4 a = *(const float4*)(v1 + j0);
        float4 b = *(const float4*)(w2 + j0);
        u1[0] = a.x; u1[1] = a.y; u1[2] = a.z; u1[3] = a.w;
        u2[0] = b.x; u2[1] = b.y; u2[2] = b.z; u2[3] = b.w;
    } else {
        #pragma unroll
        for (int t = 0; t < 4; t++) {
            u1[t] = v1[(j0 + t + 1) & 31];
            u2[t] = w2[(j0 + t + 31) & 31];
        }
    }
    *(float4*)(u1o + idx) = make_float4(u1[0], u1[1], u1[2], u1[3]);
    *(float4*)(u2o + idx) = make_float4(u2[0], u2[1], u2[2], u2[3]);
    int k = (int)(idx & 2047);
    float4 av = *(const float4*)(aC + k);
    float4 cv = *(const float4*)(cC + k);
    *(uint2*)(hi + idx) = quad_h(av.x * u1[0] + cv.x, av.y * u1[1] + cv.y,
                                 av.z * u1[2] + cv.z, av.w * u1[3] + cv.w);
    float4 y0, y1;
    if (p == 0) {
        y0 = make_float4(u1[0], u2[0], u1[1], u2[1]);
        y1 = make_float4(u1[2], u2[2], u1[3], u2[3]);
    } else {
        y0 = make_float4(u2[0], u1[0], u2[1], u1[1]);
        y1 = make_float4(u2[2], u1[2], u2[3], u1[3]);
    }
    size_t yoff = ((size_t)n << 12) + ((size_t)i << 6) + (j0 << 1);
    *(float4*)(y + yoff) = y0;
    *(float4*)(y + yoff + 4) = y1;
    if (ysl) {
        int s = n % STD;
        if (s >= 1) {
            int cc = n / STD;
            size_t so = ((size_t)(cc * 11 + s - 1) << 12) + ((size_t)i << 6) + (j0 << 1);
            *(float4*)(ysl + so) = y0;
            *(float4*)(ysl + so + 4) = y1;
        }
    }
}

// ---------------------------------------------------------------------------
// Plain mix (final outputs S2/S4)
// ---------------------------------------------------------------------------
__global__ void mix_kernel(const float* __restrict__ v1b, const float* __restrict__ w2b,
                           float* __restrict__ y)
{
    size_t q = (size_t)blockIdx.x * blockDim.x + threadIdx.x;
    if (q >= (size_t)NIMG * IMGE / 4) return;
    size_t idx = q * 4;
    int n = (int)(idx >> 12);
    int r = (int)((idx >> 6) & 63);
    int c0 = (int)(idx & 63);
    int h = c0 >> 1;
    const float* v1 = v1b + ((size_t)n << 11) + ((size_t)r << 5);
    const float* w2 = w2b + ((size_t)n << 11) + ((size_t)r << 5);
    float4 o;
    if ((r & 1) == 0) {
        float2 vv = *(const float2*)(v1 + h);
        float2 ww = *(const float2*)(w2 + h);
        o = make_float4(vv.x, ww.x, vv.y, ww.y);
    } else {
        o.x = w2[(h + 31) & 31];
        o.y = v1[(h + 1) & 31];
        o.z = w2[h];
        o.w = v1[(h + 2) & 31];
    }
    *(float4*)(y + idx) = o;
}

// ---------------------------------------------------------------------------
// Koopman step + fused split / fp16 BN-quant of the result.
// ---------------------------------------------------------------------------
__global__ void __launch_bounds__(256)
koop_kernel(const float* __restrict__ phi, const float* __restrict__ kop,
            float* __restrict__ outk,
            float* __restrict__ u1o, float* __restrict__ u2o,
            const float* __restrict__ aC, const float* __restrict__ cC,
            __half* __restrict__ hi)
{
    __shared__ float sk[64 * 64];
    __shared__ float si[64 * 68];
    int m = blockIdx.x;
    int nprime = m / STD, s = m % STD;
    int q = nprime >> 2, b = nprime & 3;
    int nin = b * 64 + q;
    const float* src = phi + (size_t)(nin * STD + s) * IMGE;
    float* dst = outk + (size_t)m * IMGE;
    int t = threadIdx.x;

    #pragma unroll
    for (int e = t * 4; e < IMGE; e += 1024)
        *(float4*)(sk + e) = *(const float4*)(kop + e);
    #pragma unroll
    for (int e = t; e < IMGE; e += 256) {
        int i = e >> 6, j = e & 63;
        si[j * 68 + i] = src[e];
    }
    __syncthreads();

    int tr = t >> 4, tc = t & 15;
    float acc[4][4];
    #pragma unroll
    for (int a = 0; a < 4; a++)
        #pragma unroll
        for (int bb = 0; bb < 4; bb++) acc[a][bb] = 0.f;

    const float* siP = si + tr * 4;
    const float* skP = sk + tc * 4;
    #pragma unroll 4
    for (int j = 0; j < 64; j++) {
        float4 av = *(const float4*)(siP + j * 68);
        float4 bv = *(const float4*)(skP + j * 64);
        acc[0][0] += av.x * bv.x; acc[0][1] += av.x * bv.y;
        acc[0][2] += av.x * bv.z; acc[0][3] += av.x * bv.w;
        acc[1][0] += av.y * bv.x; acc[1][1] += av.y * bv.y;
        acc[1][2] += av.y * bv.z; acc[1][3] += av.y * bv.w;
        acc[2][0] += av.z * bv.x; acc[2][1] += av.z * bv.y;
        acc[2][2] += av.z * bv.z; acc[2][3] += av.z * bv.w;
        acc[3][0] += av.w * bv.x; acc[3][1] += av.w * bv.y;
        acc[3][2] += av.w * bv.z; acc[3][3] += av.w * bv.w;
    }
    __syncthreads();
    float* sy = si;                   // reuse as y rows, pitch 66
    #pragma unroll
    for (int dr = 0; dr < 4; dr++) {
        int row = tr * 4 + dr;
        float4 o = make_float4(acc[dr][0], acc[dr][1], acc[dr][2], acc[dr][3]);
        *(float4*)(dst + row * 64 + tc * 4) = o;
        sy[row * 66 + tc * 4 + 0] = o.x;
        sy[row * 66 + tc * 4 + 1] = o.y;
        sy[row * 66 + tc * 4 + 2] = o.z;
        sy[row * 66 + tc * 4 + 3] = o.w;
    }
    __syncthreads();

    #pragma unroll
    for (int e8 = 0; e8 < 8; e8++) {
        int e = t + e8 * 256;
        int i = e >> 5, j = e & 31, p = i & 1;
        float uu1 = sy[i * 66 + 2 * j + p];
        float uu2 = sy[i * 66 + 2 * j + 1 - p];
        size_t go = (size_t)m * DIM + e;
        u1o[go] = uu1;
        u2o[go] = uu2;
        hi[go] = __float2half_rn(aC[e] * uu1 + cC[e]);
    }
}

// ---------------------------------------------------------------------------
// FP16 2-term GEMM (m16n8k16 + ldmatrix).
//   out[m,n] = base[m,n] + sign*( (1/64)*sum_k A[m,k]*(Whi+Wlo)[n,k] + bias[n] )
// A: single fp16 plane [M,K]; W: fp16 hi/lo planes of (64*W)^T [N,K].
// CTA tile 128x128, BK=32, 8 warps (2x4), warp tile 64x32.
// 3-stage cp.async pipeline, 90KB smem -> 2 CTAs per SM.
// ---------------------------------------------------------------------------
#define GM 128
#define GN 128
#define BK 32
#define NT_K (DIM / BK)            // 64
#define PITCHB 80
#define PLANE_B (128 * PITCHB)     // 10240
#define STAGE_B (3 * PLANE_B)      // 30720
#define STAGES 3
#define SM_TOTAL (STAGES * STAGE_B)   // 92160

__global__ void __launch_bounds__(256, 2)
gemm_tc_kernel(const __half* __restrict__ Ah, const __half* __restrict__ Whi,
               const __half* __restrict__ Wlo,
               const float* __restrict__ bias, const float* base, float* outp, float sign,
               const float* __restrict__ aN, const float* __restrict__ cN,
               __half* eHi, int emit)
{
    extern __shared__ char smem[];
    uint32_t sb = smem_u32(smem);
    const int tid  = threadIdx.x;
    const int wid  = tid >> 5;
    const int lane = tid & 31;
    const int gid  = lane >> 2;
    const int tig  = lane & 3;
    const int warpM = wid >> 2;
    const int warpN = wid & 3;
    const int m0 = blockIdx.y * GM;
    const int n0 = blockIdx.x * GN;

    float acc[4][4][4];
    #pragma unroll
    for (int i = 0; i < 4; i++)
        #pragma unroll
        for (int j = 0; j < 4; j++)
            #pragma unroll
            for (int c = 0; c < 4; c++) acc[i][j][c] = 0.f;

    const int t8 = lane >> 3;
    const int r8 = lane & 7;
    const uint32_t aoff = (uint32_t)((warpM * 64 + (t8 & 1) * 8 + r8) * PITCHB + (t8 >> 1) * 16);
    const uint32_t boff = (uint32_t)(PLANE_B +
                          (warpN * 32 + (t8 >> 1) * 8 + r8) * PITCHB + (t8 & 1) * 16);

    // loader: 3 planes x 512 chunks = 1536 chunks, 6 per thread
    auto load_tile = [&](int s, int t) {
        const int k0 = t * BK;
        uint32_t stage = sb + (uint32_t)(s * STAGE_B);
        #pragma unroll
        for (int j = 0; j < 6; j++) {
            int c = tid + j * 256;
            int pl = c >> 9;                 // 0=A, 1=Whi, 2=Wlo
            int cc = c & 511;
            int row = cc >> 2;
            int c4  = cc & 3;
            const __half* g;
            if (pl == 0)      g = Ah  + (size_t)(m0 + row) * DIM + k0 + c4 * 8;
            else if (pl == 1) g = Whi + (size_t)(n0 + row) * DIM + k0 + c4 * 8;
            else              g = Wlo + (size_t)(n0 + row) * DIM + k0 + c4 * 8;
            cp16(stage + (uint32_t)(pl * PLANE_B + row * PITCHB + c4 * 16), g);
        }
    };

    #pragma unroll
    for (int s = 0; s < STAGES; s++) {
        load_tile(s, s);
        CP_COMMIT();
    }

    for (int t = 0; t < NT_K; t++) {
        CP_WAIT(2);
        __syncthreads();
        uint32_t stg = sb + (uint32_t)((t % STAGES) * STAGE_B);
        uint32_t aB = stg + aoff;
        uint32_t bB = stg + boff;

        #pragma unroll
        for (int kk = 0; kk < BK; kk += 16) {
            uint32_t Af[4][4], Bh[4][2], Bl[4][2];
            #pragma unroll
            for (int mi = 0; mi < 4; mi++)
                ldsm4(Af[mi], aB + (uint32_t)(mi * 16 * PITCHB + kk * 2));
            #pragma unroll
            for (int nip = 0; nip < 2; nip++) {
                uint32_t b = bB + (uint32_t)(nip * 16 * PITCHB + kk * 2);
                uint32_t th[4], tl[4];
                ldsm4(th, b);
                ldsm4(tl, b + PLANE_B);
                Bh[nip * 2][0] = th[0]; Bh[nip * 2][1] = th[1];
                Bh[nip * 2 + 1][0] = th[2]; Bh[nip * 2 + 1][1] = th[3];
                Bl[nip * 2][0] = tl[0]; Bl[nip * 2][1] = tl[1];
                Bl[nip * 2 + 1][0] = tl[2]; Bl[nip * 2 + 1][1] = tl[3];
            }
            #pragma unroll
            for (int mi = 0; mi < 4; mi++)
                #pragma unroll
                for (int ni = 0; ni < 4; ni++) {
                    mma_f16(acc[mi][ni], Af[mi], Bh[ni]);
                    mma_f16(acc[mi][ni], Af[mi], Bl[ni]);
                }
        }
        __syncthreads();
        if (t + STAGES < NT_K) load_tile(t % STAGES, t + STAGES);
        CP_COMMIT();
    }

    // ---- epilogue ----
    #pragma unroll
    for (int mi = 0; mi < 4; mi++) {
        #pragma unroll
        for (int half = 0; half < 2; half++) {
            size_t m = (size_t)(m0 + warpM * 64 + mi * 16 + gid + half * 8);
            #pragma unroll
            for (int ni = 0; ni < 4; ni++) {
                int n = n0 + warpN * 32 + ni * 8 + 2 * tig;
                float r0 = acc[mi][ni][half * 2 + 0] * WSCALE_INV;
                float r1 = acc[mi][ni][half * 2 + 1] * WSCALE_INV;
                float2 bs = *(const float2*)(bias + n);
                float2 bb = *(const float2*)(base + m * DIM + n);
                float2 o;
                o.x = bb.x + sign * (r0 + bs.x);
                o.y = bb.y + sign * (r1 + bs.y);
                *(float2*)(outp + m * DIM + n) = o;
                if (emit) {
                    float2 a2 = *(const float2*)(aN + n);
                    float2 c2 = *(const float2*)(cN + n);
                    __half2 h2 = __floats2half2_rn(a2.x * o.x + c2.x, a2.y * o.y + c2.y);
                    *(__half2*)(eHi + m * DIM + n) = h2;
                }
            }
        }
    }
}

// ---------------------------------------------------------------------------
extern "C" void kernel_launch(void* const* d_in, const int* in_sizes, int n_in,
                              void* d_out, int out_size)
{
    const float* x   = (const float*)d_in[0];
    const float* W1  = (const float*)d_in[2];
    const float* b1  = (const float*)d_in[3];
    const float* g1  = (const float*)d_in[4];
    const float* be1 = (const float*)d_in[5];
    const float* m1  = (const float*)d_in[6];
    const float* v1  = (const float*)d_in[7];
    const float* W3  = (const float*)d_in[8];
    const float* b3  = (const float*)d_in[9];
    const float* g3  = (const float*)d_in[10];
    const float* be3 = (const float*)d_in[11];
    const float* m3  = (const float*)d_in[12];
    const float* v3  = (const float*)d_in[13];
    const float* kop = (const float*)d_in[14];
    float* out = (float*)d_out;

    float *A, *B, *C, *D, *aF, *cF, *aG, *cG;
    __half *H0, *H1, *W1h, *W1l, *W3h, *W3l;
    cudaGetSymbolAddress((void**)&A,  g_A);
    cudaGetSymbolAddress((void**)&B,  g_B);
    cudaGetSymbolAddress((void**)&C,  g_C);
    cudaGetSymbolAddress((void**)&D,  g_D);
    cudaGetSymbolAddress((void**)&H0, g_H0);
    cudaGetSymbolAddress((void**)&H1, g_H1);
    cudaGetSymbolAddress((void**)&W1h, g_W1Thi);
    cudaGetSymbolAddress((void**)&W1l, g_W1Tlo);
    cudaGetSymbolAddress((void**)&W3h, g_W3Thi);
    cudaGetSymbolAddress((void**)&W3l, g_W3Tlo);
    cudaGetSymbolAddress((void**)&aF, g_aF);
    cudaGetSymbolAddress((void**)&cF, g_cF);
    cudaGetSymbolAddress((void**)&aG, g_aG);
    cudaGetSymbolAddress((void**)&cG, g_cG);

    static int smem_set = 0;
    if (!smem_set) {
        cudaFuncSetAttribute(gemm_tc_kernel, cudaFuncAttributeMaxDynamicSharedMemorySize,
                             SM_TOTAL);
        smem_set = 1;
    }

    dim3 ggrid(DIM / GN, NIMG / GM);           // (16, 24)
    const int UQ_BLKS  = (int)(((size_t)NIMG * DIM / 4 + 255) / 256);
    const int MIX_BLKS = (int)(((size_t)NIMG * IMGE / 4 + 255) / 256);
    dim3 wgrid(DIM / 32, DIM / 32), wblk(32, 8);

    bncoef_kernel<<<8, 256>>>(g1, be1, m1, v1, g3, be3, m3, v3);
    wprep_kernel<<<wgrid, wblk>>>(W1, W1h, W1l);
    wprep_kernel<<<wgrid, wblk>>>(W3, W3h, W3l);

    // ---- x prep: S0, S5, u1(A), u2(B), fp16 BN_F(u2) plane ----
    xprep_kernel<<<UQ_BLKS, 256>>>(x, out + S0, out + S5, A, B, aF, cF, H0);

    // ---- Encoder ----
    gemm_tc_kernel<<<ggrid, 256, SM_TOTAL>>>(H0, W1h, W1l, b1, A, A, +1.0f,
                                             aG, cG, H1, 1);              // A = v1
    gemm_tc_kernel<<<ggrid, 256, SM_TOTAL>>>(H1, W3h, W3l, b3, B, B, +1.0f,
                                             aF, cF, H0, 0);              // B = w2
    // phiX + slice + decoder split (C=w1, D=w2) + fp16 BN_G(w1) plane
    mixsplit_kernel<<<UQ_BLKS, 256>>>(A, B, out + S1, out + S6, C, D, aG, cG, H0);

    // ---- Decoder(phiX) ----
    gemm_tc_kernel<<<ggrid, 256, SM_TOTAL>>>(H0, W3h, W3l, b3, D, D, -1.0f,
                                             aF, cF, H1, 1);              // D = v2
    gemm_tc_kernel<<<ggrid, 256, SM_TOTAL>>>(H1, W1h, W1l, b1, C, C, -1.0f,
                                             aF, cF, H0, 0);              // C = u1
    mix_kernel<<<MIX_BLKS, 256>>>(C, D, out + S2);                        // dephiPhiX

    // ---- Koopman (+ fused split of kPhix: A=w1', B=w2', fp16 BN_G(w1')) ----
    koop_kernel<<<NIMG, 256>>>(out + S1, kop, out + S3, A, B, aG, cG, H0);

    // ---- Decoder(kPhix) ----
    gemm_tc_kernel<<<ggrid, 256, SM_TOTAL>>>(H0, W3h, W3l, b3, B, B, -1.0f,
                                             aF, cF, H1, 1);              // B = v2'
    gemm_tc_kernel<<<ggrid, 256, SM_TOTAL>>>(H1, W1h, W1l, b1, A, A, -1.0f,
                                             aF, cF, H0, 0);              // A = u1'
    mix_kernel<<<MIX_BLKS, 256>>>(A, B, out + S4);                        // dePhiKPhiX
}